// round 1
// baseline (speedup 1.0000x reference)
#include <cuda_runtime.h>
#include <math.h>

// ---------------- problem constants (fixed shapes) ----------------
#define BQ   16      // batch
#define CH   256     // hidden
#define CONDC 512    // cond channels
#define TT   2048    // target length
#define TSL  512     // source length
#define NH   4       // heads
#define KC   64      // head dim

// ---------------- scratch (device globals; no allocation) ----------------
__device__ float g_c  [BQ * CH * TSL];        // cond proj           [b][C][Ts]
__device__ float g_q  [BQ * CH * TT];         // q (rope'd)          [b][C][Tt] == [bh][64][Tt]
__device__ float g_k  [BQ * CH * TSL];        // k (rope'd)          [bh][64][Ts]
__device__ float g_v  [BQ * CH * TSL];        // v                   [bh][64][Ts]
__device__ float g_vt [BQ * NH * TSL * KC];   // v transposed        [bh][Ts][64]
__device__ float g_s  [BQ * NH * TT * TSL];   // scores / probs      [bh][Tt][Ts]
__device__ float g_att[BQ * CH * TT];         // attn out            [b][C][Tt]
__device__ float g_y  [BQ * CH * TT];         // wo proj             [b][C][Tt]
__device__ float g_gb [BQ * 2 * CH * TT];     // film gamma/beta     [b][2C][Tt]
__device__ float g_cos[TT * 32];
__device__ float g_sin[TT * 32];

// ---------------- RoPE tables ----------------
// Reference: inv = 10000^(-i/32) (fp32), ang = fp32(t * inv), then cos/sin of
// that fp32 value. We reproduce the fp32 rounding of the angle, then use
// double-precision trig (immune to fast-math) for an accurate cos/sin.
__global__ void rope_table_kernel() {
    int idx = blockIdx.x * blockDim.x + threadIdx.x;
    if (idx >= TT * 32) return;
    int t = idx >> 5;
    int i = idx & 31;
    float invf = (float)pow(10000.0, -(double)i / 32.0);
    float ang  = (float)t * invf;            // same fp32 rounding as reference
    g_cos[idx] = (float)cos((double)ang);
    g_sin[idx] = (float)sin((double)ang);
}

// In-place RoPE on tensor laid out [bh][64][T]. Pair (d, d+32), angle idx d.
__global__ void rope_apply_kernel(float* __restrict__ q, int T, int total) {
    int idx = blockIdx.x * blockDim.x + threadIdx.x;
    if (idx >= total) return;
    int t  = idx % T;
    int r  = idx / T;
    int d  = r & 31;
    int bh = r >> 5;
    float c = g_cos[t * 32 + d];
    float s = g_sin[t * 32 + d];
    size_t base = ((size_t)bh * KC + d) * T + t;
    float q1 = q[base];
    float q2 = q[base + (size_t)32 * T];
    q[base]                  = q1 * c - q2 * s;
    q[base + (size_t)32 * T] = q2 * c + q1 * s;
}

// ---------------- generic NN GEMM: Y[b] = W(MxK) @ X[b](KxN) + bias ----------------
// 128x128 block, 8x8 micro-tile, 256 threads, K-tile 8. M%128==0, N%128==0, K%8==0.
template <int M, int N, int K>
__global__ __launch_bounds__(256, 2)
void gemm_nn_bias(const float* __restrict__ W, const float* __restrict__ X,
                  const float* __restrict__ bias, float* __restrict__ Y) {
    __shared__ float As[8][128];
    __shared__ float Bs[8][128];
    const int b = blockIdx.z;
    const float* Xb = X + (size_t)b * K * N;
    float*       Yb = Y + (size_t)b * M * N;
    const int tid = threadIdx.x;
    const int tm = tid >> 4, tn = tid & 15;
    const int m0 = blockIdx.y * 128, n0 = blockIdx.x * 128;

    const int am = tid >> 1, ak = (tid & 1) * 4;   // A loader: row am, 4 k's
    const int bk = tid >> 5, bn = (tid & 31) * 4;  // B loader: row bk, 4 n's

    float acc[8][8];
#pragma unroll
    for (int i = 0; i < 8; ++i)
#pragma unroll
        for (int j = 0; j < 8; ++j) acc[i][j] = 0.f;

    for (int k0 = 0; k0 < K; k0 += 8) {
        float4 av = *(const float4*)&W[(size_t)(m0 + am) * K + k0 + ak];
        float4 bv = *(const float4*)&Xb[(size_t)(k0 + bk) * N + n0 + bn];
        As[ak + 0][am] = av.x;
        As[ak + 1][am] = av.y;
        As[ak + 2][am] = av.z;
        As[ak + 3][am] = av.w;
        *(float4*)&Bs[bk][bn] = bv;
        __syncthreads();
#pragma unroll
        for (int kk = 0; kk < 8; ++kk) {
            float a[8], bb[8];
            *(float4*)(&a[0])  = *(const float4*)&As[kk][tm * 8];
            *(float4*)(&a[4])  = *(const float4*)&As[kk][tm * 8 + 4];
            *(float4*)(&bb[0]) = *(const float4*)&Bs[kk][tn * 8];
            *(float4*)(&bb[4]) = *(const float4*)&Bs[kk][tn * 8 + 4];
#pragma unroll
            for (int i = 0; i < 8; ++i)
#pragma unroll
                for (int j = 0; j < 8; ++j)
                    acc[i][j] = fmaf(a[i], bb[j], acc[i][j]);
        }
        __syncthreads();
    }

#pragma unroll
    for (int i = 0; i < 8; ++i) {
        int m = m0 + tm * 8 + i;
        float bi = bias[m];
        float4 v0, v1;
        v0.x = acc[i][0] + bi; v0.y = acc[i][1] + bi;
        v0.z = acc[i][2] + bi; v0.w = acc[i][3] + bi;
        v1.x = acc[i][4] + bi; v1.y = acc[i][5] + bi;
        v1.z = acc[i][6] + bi; v1.w = acc[i][7] + bi;
        *(float4*)&Yb[(size_t)m * N + n0 + tn * 8]     = v0;
        *(float4*)&Yb[(size_t)m * N + n0 + tn * 8 + 4] = v1;
    }
}

// ---------------- scores GEMM: S[bh] = Q[bh]^T(Tt x 64) @ K[bh](64 x Ts) ----------------
// A is stored [K=64][M=Tt] (transposed), B stored [K=64][N=Ts]. Epilogue: scale + mask.
__global__ __launch_bounds__(256, 2)
void gemm_scores(const float* __restrict__ Q, const float* __restrict__ Km,
                 const float* __restrict__ xmask, const float* __restrict__ cmask,
                 float* __restrict__ S) {
    __shared__ float As[8][128];
    __shared__ float Bs[8][128];
    const int bh = blockIdx.z;
    const int b  = bh >> 2;
    const float* A  = Q  + (size_t)bh * KC * TT;
    const float* Bm = Km + (size_t)bh * KC * TSL;
    float*       Sb = S  + (size_t)bh * TT * TSL;
    const int tid = threadIdx.x;
    const int tm = tid >> 4, tn = tid & 15;
    const int m0 = blockIdx.y * 128, n0 = blockIdx.x * 128;
    const int lk = tid >> 5, lm = (tid & 31) * 4;

    float acc[8][8];
#pragma unroll
    for (int i = 0; i < 8; ++i)
#pragma unroll
        for (int j = 0; j < 8; ++j) acc[i][j] = 0.f;

    for (int k0 = 0; k0 < KC; k0 += 8) {
        *(float4*)&As[lk][lm] = *(const float4*)&A [(size_t)(k0 + lk) * TT  + m0 + lm];
        *(float4*)&Bs[lk][lm] = *(const float4*)&Bm[(size_t)(k0 + lk) * TSL + n0 + lm];
        __syncthreads();
#pragma unroll
        for (int kk = 0; kk < 8; ++kk) {
            float a[8], bb[8];
            *(float4*)(&a[0])  = *(const float4*)&As[kk][tm * 8];
            *(float4*)(&a[4])  = *(const float4*)&As[kk][tm * 8 + 4];
            *(float4*)(&bb[0]) = *(const float4*)&Bs[kk][tn * 8];
            *(float4*)(&bb[4]) = *(const float4*)&Bs[kk][tn * 8 + 4];
#pragma unroll
            for (int i = 0; i < 8; ++i)
#pragma unroll
                for (int j = 0; j < 8; ++j)
                    acc[i][j] = fmaf(a[i], bb[j], acc[i][j]);
        }
        __syncthreads();
    }

    float xmv[8], cmv[8];
#pragma unroll
    for (int i = 0; i < 8; ++i) xmv[i] = xmask[(size_t)b * TT  + m0 + tm * 8 + i];
#pragma unroll
    for (int j = 0; j < 8; ++j) cmv[j] = cmask[(size_t)b * TSL + n0 + tn * 8 + j];

#pragma unroll
    for (int i = 0; i < 8; ++i) {
        int m = m0 + tm * 8 + i;
        float4 v0, v1;
        float* pv = &v0.x;
#pragma unroll
        for (int j = 0; j < 8; ++j) {
            float val = (xmv[i] * cmv[j] == 0.0f) ? -1e4f : acc[i][j] * 0.125f;
            if (j < 4) pv[j] = val;
            else       (&v1.x)[j - 4] = val;
        }
        *(float4*)&Sb[(size_t)m * TSL + n0 + tn * 8]     = v0;
        *(float4*)&Sb[(size_t)m * TSL + n0 + tn * 8 + 4] = v1;
    }
}

// ---------------- row softmax over 512, in place ----------------
__global__ __launch_bounds__(128)
void softmax_rows(float* __restrict__ S) {
    __shared__ float red[4];
    size_t row = blockIdx.x;
    float* p = S + row * TSL;
    int tid = threadIdx.x;
    float4 v = *(float4*)(p + tid * 4);
    float m = fmaxf(fmaxf(v.x, v.y), fmaxf(v.z, v.w));
#pragma unroll
    for (int off = 16; off > 0; off >>= 1)
        m = fmaxf(m, __shfl_xor_sync(0xffffffffu, m, off));
    if ((tid & 31) == 0) red[tid >> 5] = m;
    __syncthreads();
    m = fmaxf(fmaxf(red[0], red[1]), fmaxf(red[2], red[3]));
    v.x = expf(v.x - m); v.y = expf(v.y - m);
    v.z = expf(v.z - m); v.w = expf(v.w - m);
    float s = v.x + v.y + v.z + v.w;
#pragma unroll
    for (int off = 16; off > 0; off >>= 1)
        s += __shfl_xor_sync(0xffffffffu, s, off);
    __syncthreads();
    if ((tid & 31) == 0) red[tid >> 5] = s;
    __syncthreads();
    s = red[0] + red[1] + red[2] + red[3];
    float inv = 1.0f / s;
    v.x *= inv; v.y *= inv; v.z *= inv; v.w *= inv;
    *(float4*)(p + tid * 4) = v;
}

// ---------------- transpose V: [bh][64][Ts] -> [bh][Ts][64] ----------------
__global__ void transpose_v_kernel() {
    __shared__ float tile[32][33];
    const int bh = blockIdx.z;
    const int s0 = blockIdx.x * 32, c0 = blockIdx.y * 32;
    const float* src = g_v  + (size_t)bh * KC * TSL;
    float*       dst = g_vt + (size_t)bh * TSL * KC;
    int tx = threadIdx.x, ty = threadIdx.y;  // (32, 8)
    for (int r = ty; r < 32; r += 8)
        tile[r][tx] = src[(size_t)(c0 + r) * TSL + s0 + tx];
    __syncthreads();
    for (int r = ty; r < 32; r += 8)
        dst[(size_t)(s0 + r) * KC + c0 + tx] = tile[tx][r];
}

// ---------------- out GEMM: ATT^T[bh] = P[bh](Tt x Ts) @ Vt[bh](Ts x 64) ----------------
// 128x64 block, 8x4 micro-tile, 256 threads. Stores transposed into [bh][64][Tt].
__global__ __launch_bounds__(256, 2)
void gemm_out(const float* __restrict__ P, const float* __restrict__ Vt,
              float* __restrict__ ATT) {
    __shared__ float As[8][128];
    __shared__ float Bs[8][64];
    const int bh = blockIdx.z;
    const float* A = P  + (size_t)bh * TT * TSL;
    const float* B = Vt + (size_t)bh * TSL * KC;
    const int tid = threadIdx.x;
    const int tm = tid >> 4, tn = tid & 15;
    const int m0 = blockIdx.y * 128;
    const int am = tid >> 1, ak = (tid & 1) * 4;

    float acc[8][4];
#pragma unroll
    for (int i = 0; i < 8; ++i)
#pragma unroll
        for (int j = 0; j < 4; ++j) acc[i][j] = 0.f;

    for (int k0 = 0; k0 < TSL; k0 += 8) {
        float4 av = *(const float4*)&A[(size_t)(m0 + am) * TSL + k0 + ak];
        As[ak + 0][am] = av.x;
        As[ak + 1][am] = av.y;
        As[ak + 2][am] = av.z;
        As[ak + 3][am] = av.w;
        if (tid < 128) {
            int bkk = tid >> 4, bnn = (tid & 15) * 4;
            *(float4*)&Bs[bkk][bnn] = *(const float4*)&B[(size_t)(k0 + bkk) * KC + bnn];
        }
        __syncthreads();
#pragma unroll
        for (int kk = 0; kk < 8; ++kk) {
            float a[8], bb[4];
            *(float4*)(&a[0])  = *(const float4*)&As[kk][tm * 8];
            *(float4*)(&a[4])  = *(const float4*)&As[kk][tm * 8 + 4];
            *(float4*)(&bb[0]) = *(const float4*)&Bs[kk][tn * 4];
#pragma unroll
            for (int i = 0; i < 8; ++i)
#pragma unroll
                for (int j = 0; j < 4; ++j)
                    acc[i][j] = fmaf(a[i], bb[j], acc[i][j]);
        }
        __syncthreads();
    }

    // transposed store: ATT[(bh*64 + n)][Tt]
#pragma unroll
    for (int j = 0; j < 4; ++j) {
        float4 lo, hi;
        lo.x = acc[0][j]; lo.y = acc[1][j]; lo.z = acc[2][j]; lo.w = acc[3][j];
        hi.x = acc[4][j]; hi.y = acc[5][j]; hi.z = acc[6][j]; hi.w = acc[7][j];
        float* dst = ATT + ((size_t)bh * KC + tn * 4 + j) * TT + m0 + tm * 8;
        *(float4*)dst       = lo;
        *(float4*)(dst + 4) = hi;
    }
}

// ---------------- FiLM: out = (x * gamma + beta) * x_mask ----------------
__global__ __launch_bounds__(256)
void film_kernel(const float* __restrict__ x, const float* __restrict__ xmask,
                 float* __restrict__ out) {
    size_t i4 = ((size_t)blockIdx.x * blockDim.x + threadIdx.x) * 4;
    size_t b   = i4 / ((size_t)CH * TT);
    size_t rem = i4 - b * ((size_t)CH * TT);
    size_t c   = rem / TT;
    size_t t   = rem - c * TT;
    float4 xv = *(const float4*)(x + i4);
    float4 gv = *(const float4*)(g_gb + (b * 2 * CH + c) * TT + t);
    float4 bv = *(const float4*)(g_gb + (b * 2 * CH + CH + c) * TT + t);
    float4 mv = *(const float4*)(xmask + b * TT + t);
    float4 o;
    o.x = (xv.x * gv.x + bv.x) * mv.x;
    o.y = (xv.y * gv.y + bv.y) * mv.y;
    o.z = (xv.z * gv.z + bv.z) * mv.z;
    o.w = (xv.w * gv.w + bv.w) * mv.w;
    *(float4*)(out + i4) = o;
}

// ---------------- launch ----------------
extern "C" void kernel_launch(void* const* d_in, const int* in_sizes, int n_in,
                              void* d_out, int out_size) {
    const float* x           = (const float*)d_in[0];
    const float* x_mask      = (const float*)d_in[1];
    const float* cond_latent = (const float*)d_in[2];
    const float* cond_mask   = (const float*)d_in[3];
    const float* w_cond      = (const float*)d_in[4];
    const float* b_cond      = (const float*)d_in[5];
    const float* wq          = (const float*)d_in[6];
    const float* bq          = (const float*)d_in[7];
    const float* wk          = (const float*)d_in[8];
    const float* bk          = (const float*)d_in[9];
    const float* wv          = (const float*)d_in[10];
    const float* bv          = (const float*)d_in[11];
    const float* wo          = (const float*)d_in[12];
    const float* bo          = (const float*)d_in[13];
    const float* w_film      = (const float*)d_in[14];
    const float* b_film      = (const float*)d_in[15];
    float* out = (float*)d_out;

    float *p_c, *p_q, *p_k, *p_v, *p_vt, *p_s, *p_att, *p_y, *p_gb;
    cudaGetSymbolAddress((void**)&p_c,   g_c);
    cudaGetSymbolAddress((void**)&p_q,   g_q);
    cudaGetSymbolAddress((void**)&p_k,   g_k);
    cudaGetSymbolAddress((void**)&p_v,   g_v);
    cudaGetSymbolAddress((void**)&p_vt,  g_vt);
    cudaGetSymbolAddress((void**)&p_s,   g_s);
    cudaGetSymbolAddress((void**)&p_att, g_att);
    cudaGetSymbolAddress((void**)&p_y,   g_y);
    cudaGetSymbolAddress((void**)&p_gb,  g_gb);

    // RoPE tables (k reuses first Ts rows of the q table; identical freqs)
    rope_table_kernel<<<(TT * 32 + 255) / 256, 256>>>();

    // c = w_cond @ cond_latent + b_cond     [b][256][512]
    gemm_nn_bias<CH, TSL, CONDC><<<dim3(TSL / 128, CH / 128, BQ), 256>>>(w_cond, cond_latent, b_cond, p_c);

    // q = wq @ x + bq                        [b][256][2048]
    gemm_nn_bias<CH, TT, CH><<<dim3(TT / 128, CH / 128, BQ), 256>>>(wq, x, bq, p_q);
    // k = wk @ c + bk, v = wv @ c + bv       [b][256][512]
    gemm_nn_bias<CH, TSL, CH><<<dim3(TSL / 128, CH / 128, BQ), 256>>>(wk, p_c, bk, p_k);
    gemm_nn_bias<CH, TSL, CH><<<dim3(TSL / 128, CH / 128, BQ), 256>>>(wv, p_c, bv, p_v);

    // RoPE in place
    {
        int total_q = BQ * NH * 32 * TT;
        rope_apply_kernel<<<(total_q + 255) / 256, 256>>>(p_q, TT, total_q);
        int total_k = BQ * NH * 32 * TSL;
        rope_apply_kernel<<<(total_k + 255) / 256, 256>>>(p_k, TSL, total_k);
    }

    // V transpose for the out GEMM
    transpose_v_kernel<<<dim3(TSL / 32, KC / 32, BQ * NH), dim3(32, 8)>>>();

    // scores = (Q^T K) / 8, masked
    gemm_scores<<<dim3(TSL / 128, TT / 128, BQ * NH), 256>>>(p_q, p_k, x_mask, cond_mask, p_s);

    // softmax rows
    softmax_rows<<<BQ * NH * TT, 128>>>(p_s);

    // out = P @ Vt, stored transposed -> [b][256][2048]
    gemm_out<<<dim3(1, TT / 128, BQ * NH), 256>>>(p_s, p_vt, p_att);

    // y = wo @ att + bo
    gemm_nn_bias<CH, TT, CH><<<dim3(TT / 128, CH / 128, BQ), 256>>>(wo, p_att, bo, p_y);

    // gb = w_film @ y + b_film               [b][512][2048]
    gemm_nn_bias<2 * CH, TT, CH><<<dim3(TT / 128, 2 * CH / 128, BQ), 256>>>(w_film, p_y, b_film, p_gb);

    // out = (x * gamma + beta) * x_mask
    film_kernel<<<(BQ * CH * TT / 4 + 255) / 256, 256>>>(x, x_mask, out);
}

// round 2
// speedup vs baseline: 1.9621x; 1.9621x over previous
#include <cuda_runtime.h>
#include <math.h>
#include <stdint.h>

// ---------------- problem constants (fixed shapes) ----------------
#define BQ   16      // batch
#define CH   256     // hidden
#define CONDC 512    // cond channels
#define TT   2048    // target length
#define TSL  512     // source length
#define NH   4       // heads
#define KC   64      // head dim

#define SA 136       // padded smem stride (words): 136 mod 32 = 8 (conflict-free), *4 bytes % 16 == 0
#define SB72 72      // stride for 64-wide B tiles: 72 mod 32 = 8, *4 % 16 == 0

// ---------------- scratch (device globals; no allocation) ----------------
__device__ float g_c  [BQ * CH * TSL];        // cond proj           [b][C][Ts]
__device__ float g_q  [BQ * CH * TT];         // q (rope'd)          [bh][64][Tt]
__device__ float g_k  [BQ * CH * TSL];        // k (rope'd)          [bh][64][Ts]
__device__ float g_v  [BQ * CH * TSL];        // v                   [bh][64][Ts]
__device__ float g_vt [BQ * NH * TSL * KC];   // v transposed        [bh][Ts][64]
__device__ float g_s  [BQ * NH * TT * TSL];   // scores / probs      [bh][Tt][Ts]
__device__ float g_att[BQ * CH * TT];         // attn out            [b][C][Tt]
__device__ float g_y  [BQ * CH * TT];         // wo proj             [b][C][Tt]
__device__ float g_gb [BQ * 2 * CH * TT];     // film gamma/beta     [b][2C][Tt]
__device__ float g_cos[TT * 32];
__device__ float g_sin[TT * 32];

// ---------------- tf32 helpers ----------------
__device__ __forceinline__ uint32_t f2tf(float f) {
    uint32_t u;
    asm("cvt.rna.tf32.f32 %0, %1;" : "=r"(u) : "f"(f));
    return u;
}

__device__ __forceinline__ void mma_tf32(float* c, const uint32_t* a, const uint32_t* b) {
    asm volatile(
        "mma.sync.aligned.m16n8k8.row.col.f32.tf32.tf32.f32 "
        "{%0,%1,%2,%3}, {%4,%5,%6,%7}, {%8,%9}, {%0,%1,%2,%3};\n"
        : "+f"(c[0]), "+f"(c[1]), "+f"(c[2]), "+f"(c[3])
        : "r"(a[0]), "r"(a[1]), "r"(a[2]), "r"(a[3]), "r"(b[0]), "r"(b[1]));
}

// ---------------- RoPE tables ----------------
__global__ void rope_table_kernel() {
    int idx = blockIdx.x * blockDim.x + threadIdx.x;
    if (idx >= TT * 32) return;
    int t = idx >> 5;
    int i = idx & 31;
    float invf = (float)pow(10000.0, -(double)i / 32.0);
    float ang  = (float)t * invf;            // same fp32 rounding as reference
    g_cos[idx] = (float)cos((double)ang);
    g_sin[idx] = (float)sin((double)ang);
}

// In-place RoPE on tensor laid out [bh][64][T]. Pair (d, d+32), angle idx d.
__global__ void rope_apply_kernel(float* __restrict__ q, int T, int total) {
    int idx = blockIdx.x * blockDim.x + threadIdx.x;
    if (idx >= total) return;
    int t  = idx % T;
    int r  = idx / T;
    int d  = r & 31;
    int bh = r >> 5;
    float c = g_cos[t * 32 + d];
    float s = g_sin[t * 32 + d];
    size_t base = ((size_t)bh * KC + d) * T + t;
    float q1 = q[base];
    float q2 = q[base + (size_t)32 * T];
    q[base]                  = q1 * c - q2 * s;
    q[base + (size_t)32 * T] = q2 * c + q1 * s;
}

// ============================================================================
// Generic tf32 MMA GEMM, 128x128 CTA tile, 512 threads, BK=16, double-buffered.
// AMODE 0: A stored [K][M] global (lda = Mdim)    -> direct copy into As[k][m]
// AMODE 1: A stored [M][K] global (lda = Kdim)    -> transpose-on-load
// B always stored [K][N] global (ldb = Ndim).
// EPI 0: Y = acc + bias[m]      (aux0 = bias)
// EPI 1: scores: Y = mask ? acc*0.125 : -1e4  (aux0 = x_mask [b][Tt], aux1 = cond_mask [b][Ts], b = z>>2)
// ============================================================================
template<int AMODE, int EPI>
__global__ __launch_bounds__(512)
void mma_gemm128(const float* __restrict__ A, const float* __restrict__ B,
                 const float* __restrict__ aux0, const float* __restrict__ aux1,
                 float* __restrict__ Y,
                 int Mdim, int Ndim, int Kdim,
                 size_t strideA, size_t strideB, size_t strideY)
{
    __shared__ uint32_t As[2][16 * SA];
    __shared__ uint32_t Bs[2][16 * SA];

    const int tid = threadIdx.x;
    const int bz  = blockIdx.z;
    const float* Ab = A + (size_t)bz * strideA;
    const float* Bb = B + (size_t)bz * strideB;
    float*       Yb = Y + (size_t)bz * strideY;
    const int m0 = blockIdx.y * 128, n0 = blockIdx.x * 128;

    const int wid = tid >> 5, lane = tid & 31;
    const int wm = wid >> 2, wn = wid & 3;       // 4x4 warp grid, 32x32 warp tile
    const int r = lane >> 2, c = lane & 3;

    // loader indices
    const int l_row  = tid >> 5;          // 0..15   (B and A-KM)
    const int l_col  = (lane) * 4;        // 0..124
    const int l_am   = tid >> 2;          // 0..127  (A-MK)
    const int l_ak   = (tid & 3) * 4;     // 0,4,8,12

    float acc[2][4][4] = {};

    const int nk = Kdim / 16;

#define LOAD_TILE(k0, buf)                                                              \
    {                                                                                   \
        float4 bv = *(const float4*)&Bb[(size_t)((k0) + l_row) * Ndim + n0 + l_col];    \
        uint4 bu; bu.x = f2tf(bv.x); bu.y = f2tf(bv.y); bu.z = f2tf(bv.z); bu.w = f2tf(bv.w); \
        *(uint4*)&Bs[buf][l_row * SA + l_col] = bu;                                     \
        if (AMODE == 0) {                                                               \
            float4 av = *(const float4*)&Ab[(size_t)((k0) + l_row) * Mdim + m0 + l_col];\
            uint4 au; au.x = f2tf(av.x); au.y = f2tf(av.y); au.z = f2tf(av.z); au.w = f2tf(av.w); \
            *(uint4*)&As[buf][l_row * SA + l_col] = au;                                 \
        } else {                                                                        \
            float4 av = *(const float4*)&Ab[(size_t)(m0 + l_am) * Kdim + (k0) + l_ak];  \
            As[buf][(l_ak + 0) * SA + l_am] = f2tf(av.x);                               \
            As[buf][(l_ak + 1) * SA + l_am] = f2tf(av.y);                               \
            As[buf][(l_ak + 2) * SA + l_am] = f2tf(av.z);                               \
            As[buf][(l_ak + 3) * SA + l_am] = f2tf(av.w);                               \
        }                                                                               \
    }

    LOAD_TILE(0, 0);
    __syncthreads();

    for (int kb = 0; kb < nk; ++kb) {
        const int cur = kb & 1;
        if (kb + 1 < nk) LOAD_TILE((kb + 1) * 16, cur ^ 1);

#pragma unroll
        for (int k8 = 0; k8 < 16; k8 += 8) {
            uint32_t af[2][4], bf[4][2];
#pragma unroll
            for (int mt = 0; mt < 2; ++mt) {
                int mb = wm * 32 + mt * 16 + r;
                af[mt][0] = As[cur][(k8 + c) * SA + mb];
                af[mt][1] = As[cur][(k8 + c) * SA + mb + 8];
                af[mt][2] = As[cur][(k8 + c + 4) * SA + mb];
                af[mt][3] = As[cur][(k8 + c + 4) * SA + mb + 8];
            }
#pragma unroll
            for (int nt = 0; nt < 4; ++nt) {
                int nb = wn * 32 + nt * 8 + r;
                bf[nt][0] = Bs[cur][(k8 + c) * SA + nb];
                bf[nt][1] = Bs[cur][(k8 + c + 4) * SA + nb];
            }
#pragma unroll
            for (int mt = 0; mt < 2; ++mt)
#pragma unroll
                for (int nt = 0; nt < 4; ++nt)
                    mma_tf32(acc[mt][nt], af[mt], bf[nt]);
        }
        __syncthreads();
    }
#undef LOAD_TILE

    // epilogue
    const int bb = bz >> 2;   // batch for masks (EPI==1)
#pragma unroll
    for (int mt = 0; mt < 2; ++mt) {
#pragma unroll
        for (int h = 0; h < 2; ++h) {
            const int row = m0 + wm * 32 + mt * 16 + r + h * 8;
            float bval = 0.f, xmv = 0.f;
            if (EPI == 0) bval = aux0[row];
            else          xmv  = aux0[(size_t)bb * TT + row];
#pragma unroll
            for (int nt = 0; nt < 4; ++nt) {
                const int col = n0 + wn * 32 + nt * 8 + c * 2;
                float v0 = acc[mt][nt][h * 2 + 0];
                float v1 = acc[mt][nt][h * 2 + 1];
                if (EPI == 0) {
                    v0 += bval; v1 += bval;
                } else {
                    float cm0 = aux1[(size_t)bb * TSL + col];
                    float cm1 = aux1[(size_t)bb * TSL + col + 1];
                    v0 = (xmv * cm0 == 0.0f) ? -1e4f : v0 * 0.125f;
                    v1 = (xmv * cm1 == 0.0f) ? -1e4f : v1 * 0.125f;
                }
                float2 o; o.x = v0; o.y = v1;
                *(float2*)&Yb[(size_t)row * Ndim + col] = o;
            }
        }
    }
}

// ============================================================================
// Out GEMM: ATT^T = P(Tt x Ts) @ Vt(Ts x 64), 128x64 tile, 256 threads, BK=16.
// A = P [M][K] (lda=TSL), B = Vt [K][N=64]. Transposed scatter store -> [bh][64][Tt].
// ============================================================================
__global__ __launch_bounds__(256)
void mma_gemm_out(const float* __restrict__ P, const float* __restrict__ Vt,
                  float* __restrict__ ATT)
{
    __shared__ uint32_t As[2][16 * SA];
    __shared__ uint32_t Bs[2][16 * SB72];

    const int tid = threadIdx.x;
    const int bh  = blockIdx.z;
    const float* Ab = P  + (size_t)bh * TT * TSL;
    const float* Bb = Vt + (size_t)bh * TSL * KC;
    const int m0 = blockIdx.y * 128;

    const int wid = tid >> 5, lane = tid & 31;
    const int wm = wid >> 1, wn = wid & 1;    // 4x2 warp grid, 32x32 warp tile
    const int r = lane >> 2, c = lane & 3;

    // loaders
    const int a_m = tid >> 2;            // +it*64
    const int a_k = (tid & 3) * 4;
    const int b_row = tid >> 4;          // 0..15
    const int b_col = (tid & 15) * 4;    // 0..60

    float acc[2][4][4] = {};

#define LOAD_TILE_O(k0, buf)                                                              \
    {                                                                                     \
        float4 bv = *(const float4*)&Bb[(size_t)((k0) + b_row) * KC + b_col];             \
        uint4 bu; bu.x = f2tf(bv.x); bu.y = f2tf(bv.y); bu.z = f2tf(bv.z); bu.w = f2tf(bv.w); \
        *(uint4*)&Bs[buf][b_row * SB72 + b_col] = bu;                                     \
        _Pragma("unroll")                                                                 \
        for (int it = 0; it < 2; ++it) {                                                  \
            float4 av = *(const float4*)&Ab[(size_t)(m0 + a_m + it * 64) * TSL + (k0) + a_k]; \
            As[buf][(a_k + 0) * SA + a_m + it * 64] = f2tf(av.x);                         \
            As[buf][(a_k + 1) * SA + a_m + it * 64] = f2tf(av.y);                         \
            As[buf][(a_k + 2) * SA + a_m + it * 64] = f2tf(av.z);                         \
            As[buf][(a_k + 3) * SA + a_m + it * 64] = f2tf(av.w);                         \
        }                                                                                 \
    }

    LOAD_TILE_O(0, 0);
    __syncthreads();

    const int nk = TSL / 16;   // 32
    for (int kb = 0; kb < nk; ++kb) {
        const int cur = kb & 1;
        if (kb + 1 < nk) LOAD_TILE_O((kb + 1) * 16, cur ^ 1);

#pragma unroll
        for (int k8 = 0; k8 < 16; k8 += 8) {
            uint32_t af[2][4], bf[4][2];
#pragma unroll
            for (int mt = 0; mt < 2; ++mt) {
                int mb = wm * 32 + mt * 16 + r;
                af[mt][0] = As[cur][(k8 + c) * SA + mb];
                af[mt][1] = As[cur][(k8 + c) * SA + mb + 8];
                af[mt][2] = As[cur][(k8 + c + 4) * SA + mb];
                af[mt][3] = As[cur][(k8 + c + 4) * SA + mb + 8];
            }
#pragma unroll
            for (int nt = 0; nt < 4; ++nt) {
                int nb = wn * 32 + nt * 8 + r;
                bf[nt][0] = Bs[cur][(k8 + c) * SB72 + nb];
                bf[nt][1] = Bs[cur][(k8 + c + 4) * SB72 + nb];
            }
#pragma unroll
            for (int mt = 0; mt < 2; ++mt)
#pragma unroll
                for (int nt = 0; nt < 4; ++nt)
                    mma_tf32(acc[mt][nt], af[mt], bf[nt]);
        }
        __syncthreads();
    }
#undef LOAD_TILE_O

    // transposed scatter store: ATT[(bh*64 + col)*TT + row]
#pragma unroll
    for (int mt = 0; mt < 2; ++mt) {
#pragma unroll
        for (int h = 0; h < 2; ++h) {
            const int row = m0 + wm * 32 + mt * 16 + r + h * 8;
#pragma unroll
            for (int nt = 0; nt < 4; ++nt) {
                const int col = wn * 32 + nt * 8 + c * 2;
                ATT[((size_t)bh * KC + col)     * TT + row] = acc[mt][nt][h * 2 + 0];
                ATT[((size_t)bh * KC + col + 1) * TT + row] = acc[mt][nt][h * 2 + 1];
            }
        }
    }
}

// ---------------- row softmax over 512, in place ----------------
__global__ __launch_bounds__(128)
void softmax_rows(float* __restrict__ S) {
    __shared__ float red[4];
    size_t row = blockIdx.x;
    float* p = S + row * TSL;
    int tid = threadIdx.x;
    float4 v = *(float4*)(p + tid * 4);
    float m = fmaxf(fmaxf(v.x, v.y), fmaxf(v.z, v.w));
#pragma unroll
    for (int off = 16; off > 0; off >>= 1)
        m = fmaxf(m, __shfl_xor_sync(0xffffffffu, m, off));
    if ((tid & 31) == 0) red[tid >> 5] = m;
    __syncthreads();
    m = fmaxf(fmaxf(red[0], red[1]), fmaxf(red[2], red[3]));
    v.x = expf(v.x - m); v.y = expf(v.y - m);
    v.z = expf(v.z - m); v.w = expf(v.w - m);
    float s = v.x + v.y + v.z + v.w;
#pragma unroll
    for (int off = 16; off > 0; off >>= 1)
        s += __shfl_xor_sync(0xffffffffu, s, off);
    __syncthreads();
    if ((tid & 31) == 0) red[tid >> 5] = s;
    __syncthreads();
    s = red[0] + red[1] + red[2] + red[3];
    float inv = 1.0f / s;
    v.x *= inv; v.y *= inv; v.z *= inv; v.w *= inv;
    *(float4*)(p + tid * 4) = v;
}

// ---------------- transpose V: [bh][64][Ts] -> [bh][Ts][64] ----------------
__global__ void transpose_v_kernel() {
    __shared__ float tile[32][33];
    const int bh = blockIdx.z;
    const int s0 = blockIdx.x * 32, c0 = blockIdx.y * 32;
    const float* src = g_v  + (size_t)bh * KC * TSL;
    float*       dst = g_vt + (size_t)bh * TSL * KC;
    int tx = threadIdx.x, ty = threadIdx.y;  // (32, 8)
    for (int r = ty; r < 32; r += 8)
        tile[r][tx] = src[(size_t)(c0 + r) * TSL + s0 + tx];
    __syncthreads();
    for (int r = ty; r < 32; r += 8)
        dst[(size_t)(s0 + r) * KC + c0 + tx] = tile[tx][r];
}

// ---------------- FiLM: out = (x * gamma + beta) * x_mask ----------------
__global__ __launch_bounds__(256)
void film_kernel(const float* __restrict__ x, const float* __restrict__ xmask,
                 float* __restrict__ out) {
    size_t i4 = ((size_t)blockIdx.x * blockDim.x + threadIdx.x) * 4;
    size_t b   = i4 / ((size_t)CH * TT);
    size_t rem = i4 - b * ((size_t)CH * TT);
    size_t c   = rem / TT;
    size_t t   = rem - c * TT;
    float4 xv = *(const float4*)(x + i4);
    float4 gv = *(const float4*)(g_gb + (b * 2 * CH + c) * TT + t);
    float4 bv = *(const float4*)(g_gb + (b * 2 * CH + CH + c) * TT + t);
    float4 mv = *(const float4*)(xmask + b * TT + t);
    float4 o;
    o.x = (xv.x * gv.x + bv.x) * mv.x;
    o.y = (xv.y * gv.y + bv.y) * mv.y;
    o.z = (xv.z * gv.z + bv.z) * mv.z;
    o.w = (xv.w * gv.w + bv.w) * mv.w;
    *(float4*)(out + i4) = o;
}

// ---------------- launch ----------------
extern "C" void kernel_launch(void* const* d_in, const int* in_sizes, int n_in,
                              void* d_out, int out_size) {
    const float* x           = (const float*)d_in[0];
    const float* x_mask      = (const float*)d_in[1];
    const float* cond_latent = (const float*)d_in[2];
    const float* cond_mask   = (const float*)d_in[3];
    const float* w_cond      = (const float*)d_in[4];
    const float* b_cond      = (const float*)d_in[5];
    const float* wq          = (const float*)d_in[6];
    const float* bq          = (const float*)d_in[7];
    const float* wk          = (const float*)d_in[8];
    const float* bk          = (const float*)d_in[9];
    const float* wv          = (const float*)d_in[10];
    const float* bv          = (const float*)d_in[11];
    const float* wo          = (const float*)d_in[12];
    const float* bo          = (const float*)d_in[13];
    const float* w_film      = (const float*)d_in[14];
    const float* b_film      = (const float*)d_in[15];
    float* out = (float*)d_out;

    float *p_c, *p_q, *p_k, *p_v, *p_vt, *p_s, *p_att, *p_y, *p_gb;
    cudaGetSymbolAddress((void**)&p_c,   g_c);
    cudaGetSymbolAddress((void**)&p_q,   g_q);
    cudaGetSymbolAddress((void**)&p_k,   g_k);
    cudaGetSymbolAddress((void**)&p_v,   g_v);
    cudaGetSymbolAddress((void**)&p_vt,  g_vt);
    cudaGetSymbolAddress((void**)&p_s,   g_s);
    cudaGetSymbolAddress((void**)&p_att, g_att);
    cudaGetSymbolAddress((void**)&p_y,   g_y);
    cudaGetSymbolAddress((void**)&p_gb,  g_gb);

    // RoPE tables
    rope_table_kernel<<<(TT * 32 + 255) / 256, 256>>>();

    // c = w_cond @ cond_latent + b_cond     [b][256][512]
    mma_gemm128<1, 0><<<dim3(TSL / 128, CH / 128, BQ), 512>>>(
        w_cond, cond_latent, b_cond, nullptr, p_c,
        CH, TSL, CONDC, 0, (size_t)CONDC * TSL, (size_t)CH * TSL);

    // q = wq @ x + bq                        [b][256][2048]
    mma_gemm128<1, 0><<<dim3(TT / 128, CH / 128, BQ), 512>>>(
        wq, x, bq, nullptr, p_q,
        CH, TT, CH, 0, (size_t)CH * TT, (size_t)CH * TT);

    // k = wk @ c + bk ; v = wv @ c + bv      [b][256][512]
    mma_gemm128<1, 0><<<dim3(TSL / 128, CH / 128, BQ), 512>>>(
        wk, p_c, bk, nullptr, p_k,
        CH, TSL, CH, 0, (size_t)CH * TSL, (size_t)CH * TSL);
    mma_gemm128<1, 0><<<dim3(TSL / 128, CH / 128, BQ), 512>>>(
        wv, p_c, bv, nullptr, p_v,
        CH, TSL, CH, 0, (size_t)CH * TSL, (size_t)CH * TSL);

    // RoPE in place
    {
        int total_q = BQ * NH * 32 * TT;
        rope_apply_kernel<<<(total_q + 255) / 256, 256>>>(p_q, TT, total_q);
        int total_k = BQ * NH * 32 * TSL;
        rope_apply_kernel<<<(total_k + 255) / 256, 256>>>(p_k, TSL, total_k);
    }

    // V transpose for the out GEMM
    transpose_v_kernel<<<dim3(TSL / 32, KC / 32, BQ * NH), dim3(32, 8)>>>();

    // scores = mask((Q^T K) / 8)             [bh][2048][512]
    mma_gemm128<0, 1><<<dim3(TSL / 128, TT / 128, BQ * NH), 512>>>(
        p_q, p_k, x_mask, cond_mask, p_s,
        TT, TSL, KC, (size_t)KC * TT, (size_t)KC * TSL, (size_t)TT * TSL);

    // softmax rows
    softmax_rows<<<BQ * NH * TT, 128>>>(p_s);

    // out = P @ Vt, stored transposed -> [b][256][2048]
    mma_gemm_out<<<dim3(1, TT / 128, BQ * NH), 256>>>(p_s, p_vt, p_att);

    // y = wo @ att + bo
    mma_gemm128<1, 0><<<dim3(TT / 128, CH / 128, BQ), 512>>>(
        wo, p_att, bo, nullptr, p_y,
        CH, TT, CH, 0, (size_t)CH * TT, (size_t)CH * TT);

    // gb = w_film @ y + b_film               [b][512][2048]
    mma_gemm128<1, 0><<<dim3(TT / 128, 2 * CH / 128, BQ), 512>>>(
        w_film, p_y, b_film, nullptr, p_gb,
        2 * CH, TT, CH, 0, (size_t)CH * TT, (size_t)2 * CH * TT);

    // out = (x * gamma + beta) * x_mask
    film_kernel<<<(BQ * CH * TT / 4 + 255) / 256, 256>>>(x, x_mask, out);
}

// round 3
// speedup vs baseline: 2.5496x; 1.2994x over previous
#include <cuda_runtime.h>
#include <math.h>
#include <stdint.h>

// ---------------- problem constants (fixed shapes) ----------------
#define BQ   16      // batch
#define CH   256     // hidden
#define CONDC 512    // cond channels
#define TT   2048    // target length
#define TSL  512     // source length
#define NH   4       // heads
#define KC   64      // head dim

#define SA 136       // padded smem stride (words): mod 32 = 8 (CF fragment loads), *4 % 16 == 0

// ---------------- scratch (device globals; no allocation) ----------------
__device__ float g_c  [BQ * CH * TSL];        // cond proj           [b][C][Ts]
__device__ float g_q  [BQ * CH * TT];         // q (un-roped)        [bh][64][Tt]
__device__ float g_k  [BQ * CH * TSL];        // k (un-roped)        [bh][64][Ts]
__device__ float g_v  [BQ * CH * TSL];        // v                   [bh][64][Ts]
__device__ float g_att[BQ * CH * TT];         // attn out            [b][C][Tt]
__device__ float g_y  [BQ * CH * TT];         // wo proj             [b][C][Tt]
__device__ float g_cos[32 * TT];              // [d][t]
__device__ float g_sin[32 * TT];

// ---------------- tf32 helpers ----------------
__device__ __forceinline__ uint32_t f2tf(float f) {
    uint32_t u;
    asm("cvt.rna.tf32.f32 %0, %1;" : "=r"(u) : "f"(f));
    return u;
}

__device__ __forceinline__ void mma_tf32(float* c, const uint32_t* a, const uint32_t* b) {
    asm volatile(
        "mma.sync.aligned.m16n8k8.row.col.f32.tf32.tf32.f32 "
        "{%0,%1,%2,%3}, {%4,%5,%6,%7}, {%8,%9}, {%0,%1,%2,%3};\n"
        : "+f"(c[0]), "+f"(c[1]), "+f"(c[2]), "+f"(c[3])
        : "r"(a[0]), "r"(a[1]), "r"(a[2]), "r"(a[3]), "r"(b[0]), "r"(b[1]));
}

// ---------------- RoPE tables, layout [d][t] for coalesced float4 reads ----
__global__ void rope_table_kernel() {
    int idx = blockIdx.x * blockDim.x + threadIdx.x;
    if (idx >= 32 * TT) return;
    int d = idx / TT;
    int t = idx % TT;
    float invf = (float)pow(10000.0, -(double)d / 32.0);
    float ang  = (float)t * invf;            // same fp32 rounding as reference
    g_cos[idx] = (float)cos((double)ang);
    g_sin[idx] = (float)sin((double)ang);
}

// ============================================================================
// Generic tf32 MMA GEMM, 128x128 CTA tile, 512 threads, BK=16, double-buffered.
// AMODE 1: A stored [M][K] global (lda = Kdim) -> transpose-on-load.
// EPI 0: Y = acc + bias[m]
// ============================================================================
template<int AMODE, int EPI>
__global__ __launch_bounds__(512)
void mma_gemm128(const float* __restrict__ A, const float* __restrict__ B,
                 const float* __restrict__ aux0, const float* __restrict__ aux1,
                 float* __restrict__ Y,
                 int Mdim, int Ndim, int Kdim,
                 size_t strideA, size_t strideB, size_t strideY)
{
    __shared__ uint32_t As[2][16 * SA];
    __shared__ uint32_t Bs[2][16 * SA];

    const int tid = threadIdx.x;
    const int bz  = blockIdx.z;
    const float* Ab = A + (size_t)bz * strideA;
    const float* Bb = B + (size_t)bz * strideB;
    float*       Yb = Y + (size_t)bz * strideY;
    const int m0 = blockIdx.y * 128, n0 = blockIdx.x * 128;

    const int wid = tid >> 5, lane = tid & 31;
    const int wm = wid >> 2, wn = wid & 3;       // 4x4 warp grid, 32x32 warp tile
    const int r = lane >> 2, c = lane & 3;

    const int l_row  = tid >> 5;          // 0..15
    const int l_col  = (lane) * 4;        // 0..124
    const int l_am   = tid >> 2;          // 0..127
    const int l_ak   = (tid & 3) * 4;     // 0,4,8,12

    float acc[2][4][4] = {};
    const int nk = Kdim / 16;

#define LOAD_TILE(k0, buf)                                                              \
    {                                                                                   \
        float4 bv = *(const float4*)&Bb[(size_t)((k0) + l_row) * Ndim + n0 + l_col];    \
        uint4 bu; bu.x = f2tf(bv.x); bu.y = f2tf(bv.y); bu.z = f2tf(bv.z); bu.w = f2tf(bv.w); \
        *(uint4*)&Bs[buf][l_row * SA + l_col] = bu;                                     \
        if (AMODE == 0) {                                                               \
            float4 av = *(const float4*)&Ab[(size_t)((k0) + l_row) * Mdim + m0 + l_col];\
            uint4 au; au.x = f2tf(av.x); au.y = f2tf(av.y); au.z = f2tf(av.z); au.w = f2tf(av.w); \
            *(uint4*)&As[buf][l_row * SA + l_col] = au;                                 \
        } else {                                                                        \
            float4 av = *(const float4*)&Ab[(size_t)(m0 + l_am) * Kdim + (k0) + l_ak];  \
            As[buf][(l_ak + 0) * SA + l_am] = f2tf(av.x);                               \
            As[buf][(l_ak + 1) * SA + l_am] = f2tf(av.y);                               \
            As[buf][(l_ak + 2) * SA + l_am] = f2tf(av.z);                               \
            As[buf][(l_ak + 3) * SA + l_am] = f2tf(av.w);                               \
        }                                                                               \
    }

    LOAD_TILE(0, 0);
    __syncthreads();

    for (int kb = 0; kb < nk; ++kb) {
        const int cur = kb & 1;
        if (kb + 1 < nk) LOAD_TILE((kb + 1) * 16, cur ^ 1);

#pragma unroll
        for (int k8 = 0; k8 < 16; k8 += 8) {
            uint32_t af[2][4], bf[4][2];
#pragma unroll
            for (int mt = 0; mt < 2; ++mt) {
                int mb = wm * 32 + mt * 16 + r;
                af[mt][0] = As[cur][(k8 + c) * SA + mb];
                af[mt][1] = As[cur][(k8 + c) * SA + mb + 8];
                af[mt][2] = As[cur][(k8 + c + 4) * SA + mb];
                af[mt][3] = As[cur][(k8 + c + 4) * SA + mb + 8];
            }
#pragma unroll
            for (int nt = 0; nt < 4; ++nt) {
                int nb = wn * 32 + nt * 8 + r;
                bf[nt][0] = Bs[cur][(k8 + c) * SA + nb];
                bf[nt][1] = Bs[cur][(k8 + c + 4) * SA + nb];
            }
#pragma unroll
            for (int mt = 0; mt < 2; ++mt)
#pragma unroll
                for (int nt = 0; nt < 4; ++nt)
                    mma_tf32(acc[mt][nt], af[mt], bf[nt]);
        }
        __syncthreads();
    }
#undef LOAD_TILE

#pragma unroll
    for (int mt = 0; mt < 2; ++mt) {
#pragma unroll
        for (int h = 0; h < 2; ++h) {
            const int row = m0 + wm * 32 + mt * 16 + r + h * 8;
            float bval = aux0[row];
#pragma unroll
            for (int nt = 0; nt < 4; ++nt) {
                const int col = n0 + wn * 32 + nt * 8 + c * 2;
                float2 o;
                o.x = acc[mt][nt][h * 2 + 0] + bval;
                o.y = acc[mt][nt][h * 2 + 1] + bval;
                *(float2*)&Yb[(size_t)row * Ndim + col] = o;
            }
        }
    }
    (void)aux1;
}

// ============================================================================
// Fused flash attention (tf32 MMA), RoPE on load, online softmax.
// Per CTA: (bh, m-tile of 128 q rows). 256 threads = 8 warps, each warp owns
// 16 rows -> row reductions are warp-local. Chunks of 64 source positions.
// Output stored transposed -> [bh][64][Tt] (== [b][C][Tt]).
// smem: Qs[64][136] | Ks[64][72] | Vs[64][68] | Ps[64][136]  (tf32 words)
// ============================================================================
#define FSA 136
#define FSK 72
#define FSV 68
#define FLASH_SMEM ((64*FSA + 64*FSK + 64*FSV + 64*FSA) * 4)

__global__ __launch_bounds__(256, 2)
void flash_attn(const float* __restrict__ Qg, const float* __restrict__ Kg,
                const float* __restrict__ Vg, const float* __restrict__ xmask,
                const float* __restrict__ cmask, float* __restrict__ O)
{
    extern __shared__ uint32_t sm[];
    uint32_t* Qs = sm;                    // [64][136]
    uint32_t* Ks = sm + 64 * FSA;         // [64][72]
    uint32_t* Vs = Ks + 64 * FSK;         // [64][68]  layout [n][k]
    uint32_t* Ps = Vs + 64 * FSV;         // [64][136] layout [k][m]

    const int bh = blockIdx.z;
    const int b  = bh >> 2;
    const int m0 = blockIdx.y * 128;
    const int tid = threadIdx.x, wid = tid >> 5, lane = tid & 31;
    const int r = lane >> 2, c = lane & 3;
    const int mb = wid * 16 + r;

    const float* Qb = Qg + (size_t)bh * KC * TT;
    const float* Kb = Kg + (size_t)bh * KC * TSL;
    const float* Vb = Vg + (size_t)bh * KC * TSL;

    // ---- load Q tile (64 x 128) with RoPE ----
    {
        int d  = tid >> 3;          // 0..31
        int mg = (tid & 7) * 16;
#pragma unroll
        for (int j = 0; j < 16; j += 4) {
            int m = mg + j;
            int t = m0 + m;
            float4 q1 = *(const float4*)&Qb[(size_t)d * TT + t];
            float4 q2 = *(const float4*)&Qb[(size_t)(d + 32) * TT + t];
            float4 cv = *(const float4*)&g_cos[(size_t)d * TT + t];
            float4 sv = *(const float4*)&g_sin[(size_t)d * TT + t];
            Qs[d * FSA + m + 0] = f2tf(q1.x * cv.x - q2.x * sv.x);
            Qs[d * FSA + m + 1] = f2tf(q1.y * cv.y - q2.y * sv.y);
            Qs[d * FSA + m + 2] = f2tf(q1.z * cv.z - q2.z * sv.z);
            Qs[d * FSA + m + 3] = f2tf(q1.w * cv.w - q2.w * sv.w);
            Qs[(d + 32) * FSA + m + 0] = f2tf(q2.x * cv.x + q1.x * sv.x);
            Qs[(d + 32) * FSA + m + 1] = f2tf(q2.y * cv.y + q1.y * sv.y);
            Qs[(d + 32) * FSA + m + 2] = f2tf(q2.z * cv.z + q1.z * sv.z);
            Qs[(d + 32) * FSA + m + 3] = f2tf(q2.w * cv.w + q1.w * sv.w);
        }
    }

    const float xm0 = xmask[(size_t)b * TT + m0 + wid * 16 + r];
    const float xm1 = xmask[(size_t)b * TT + m0 + wid * 16 + r + 8];

    float m_run[2] = {-1e30f, -1e30f};
    float l_run[2] = {0.f, 0.f};
    float acc_o[8][4] = {};

    for (int s0 = 0; s0 < TSL; s0 += 64) {
        __syncthreads();   // prev-chunk K/V readers done (and Q stores, 1st iter)

        // ---- load K chunk (64 x 64) with RoPE ----
        {
            int d  = tid >> 3;          // 0..31
            int ng = (tid & 7) * 8;
#pragma unroll
            for (int j = 0; j < 8; j += 4) {
                int n = ng + j;
                int s = s0 + n;
                float4 k1 = *(const float4*)&Kb[(size_t)d * TSL + s];
                float4 k2 = *(const float4*)&Kb[(size_t)(d + 32) * TSL + s];
                float4 cv = *(const float4*)&g_cos[(size_t)d * TT + s];
                float4 sv = *(const float4*)&g_sin[(size_t)d * TT + s];
                Ks[d * FSK + n + 0] = f2tf(k1.x * cv.x - k2.x * sv.x);
                Ks[d * FSK + n + 1] = f2tf(k1.y * cv.y - k2.y * sv.y);
                Ks[d * FSK + n + 2] = f2tf(k1.z * cv.z - k2.z * sv.z);
                Ks[d * FSK + n + 3] = f2tf(k1.w * cv.w - k2.w * sv.w);
                Ks[(d + 32) * FSK + n + 0] = f2tf(k2.x * cv.x + k1.x * sv.x);
                Ks[(d + 32) * FSK + n + 1] = f2tf(k2.y * cv.y + k1.y * sv.y);
                Ks[(d + 32) * FSK + n + 2] = f2tf(k2.z * cv.z + k1.z * sv.z);
                Ks[(d + 32) * FSK + n + 3] = f2tf(k2.w * cv.w + k1.w * sv.w);
            }
        }
        // ---- load V chunk: Vs[n][k] = V[channel n][pos s0+k] ----
        {
            int n  = tid >> 2;          // 0..63
            int kg = (tid & 3) * 16;
#pragma unroll
            for (int j = 0; j < 16; j += 4) {
                int k = kg + j;
                float4 vv = *(const float4*)&Vb[(size_t)n * TSL + s0 + k];
                Vs[n * FSV + k + 0] = f2tf(vv.x);
                Vs[n * FSV + k + 1] = f2tf(vv.y);
                Vs[n * FSV + k + 2] = f2tf(vv.z);
                Vs[n * FSV + k + 3] = f2tf(vv.w);
            }
        }
        __syncthreads();

        // ---- S = Q^T K : warp tile 16 x 64 ----
        float acc_s[8][4] = {};
#pragma unroll
        for (int k8 = 0; k8 < 64; k8 += 8) {
            uint32_t af[4];
            af[0] = Qs[(k8 + c) * FSA + mb];
            af[1] = Qs[(k8 + c) * FSA + mb + 8];
            af[2] = Qs[(k8 + c + 4) * FSA + mb];
            af[3] = Qs[(k8 + c + 4) * FSA + mb + 8];
#pragma unroll
            for (int nt = 0; nt < 8; ++nt) {
                uint32_t bf[2];
                bf[0] = Ks[(k8 + c) * FSK + nt * 8 + r];
                bf[1] = Ks[(k8 + c + 4) * FSK + nt * 8 + r];
                mma_tf32(acc_s[nt], af, bf);
            }
        }

        // ---- mask + scale + online softmax (warp-local rows) ----
        float mx[2] = {-1e30f, -1e30f};
#pragma unroll
        for (int nt = 0; nt < 8; ++nt) {
#pragma unroll
            for (int jj = 0; jj < 4; ++jj) {
                int col = s0 + nt * 8 + 2 * c + (jj & 1);
                float cm = cmask[(size_t)b * TSL + col];
                float xm = (jj < 2) ? xm0 : xm1;
                float v = (xm * cm == 0.f) ? -1e4f : acc_s[nt][jj] * 0.125f;
                acc_s[nt][jj] = v;
                mx[jj >> 1] = fmaxf(mx[jj >> 1], v);
            }
        }
#pragma unroll
        for (int h = 0; h < 2; ++h) {
            mx[h] = fmaxf(mx[h], __shfl_xor_sync(0xffffffffu, mx[h], 1));
            mx[h] = fmaxf(mx[h], __shfl_xor_sync(0xffffffffu, mx[h], 2));
        }
        float mnew[2], scale[2], lad[2] = {0.f, 0.f};
#pragma unroll
        for (int h = 0; h < 2; ++h) {
            mnew[h]  = fmaxf(m_run[h], mx[h]);
            scale[h] = __expf(m_run[h] - mnew[h]);
            m_run[h] = mnew[h];
        }
#pragma unroll
        for (int nt = 0; nt < 8; ++nt) {
#pragma unroll
            for (int jj = 0; jj < 4; ++jj) {
                float e = __expf(acc_s[nt][jj] - mnew[jj >> 1]);
                acc_s[nt][jj] = e;
                lad[jj >> 1] += e;
            }
        }
#pragma unroll
        for (int h = 0; h < 2; ++h) {
            lad[h] += __shfl_xor_sync(0xffffffffu, lad[h], 1);
            lad[h] += __shfl_xor_sync(0xffffffffu, lad[h], 2);
            l_run[h] = l_run[h] * scale[h] + lad[h];
        }
        // rescale accumulated output
#pragma unroll
        for (int nt = 0; nt < 8; ++nt) {
#pragma unroll
            for (int jj = 0; jj < 4; ++jj)
                acc_o[nt][jj] *= scale[jj >> 1];
        }
        // store P -> smem [k][m] (warp-private column stripe)
#pragma unroll
        for (int nt = 0; nt < 8; ++nt) {
#pragma unroll
            for (int jj = 0; jj < 4; ++jj) {
                int kcol = nt * 8 + 2 * c + (jj & 1);
                int mrow = wid * 16 + r + (jj >> 1) * 8;
                Ps[kcol * FSA + mrow] = f2tf(acc_s[nt][jj]);
            }
        }
        __syncwarp();

        // ---- O += P @ V^T : warp tile 16 x 64, K = 64 ----
#pragma unroll
        for (int k8 = 0; k8 < 64; k8 += 8) {
            uint32_t af[4];
            af[0] = Ps[(k8 + c) * FSA + mb];
            af[1] = Ps[(k8 + c) * FSA + mb + 8];
            af[2] = Ps[(k8 + c + 4) * FSA + mb];
            af[3] = Ps[(k8 + c + 4) * FSA + mb + 8];
#pragma unroll
            for (int nt = 0; nt < 8; ++nt) {
                uint32_t bf[2];
                bf[0] = Vs[(nt * 8 + r) * FSV + k8 + c];
                bf[1] = Vs[(nt * 8 + r) * FSV + k8 + c + 4];
                mma_tf32(acc_o[nt], af, bf);
            }
        }
    }

    // ---- epilogue: divide by l, transposed scatter store ----
    float inv[2] = {1.f / l_run[0], 1.f / l_run[1]};
#pragma unroll
    for (int nt = 0; nt < 8; ++nt) {
#pragma unroll
        for (int jj = 0; jj < 4; ++jj) {
            int n   = nt * 8 + 2 * c + (jj & 1);
            int row = m0 + wid * 16 + r + (jj >> 1) * 8;
            O[((size_t)bh * KC + n) * TT + row] = acc_o[nt][jj] * inv[jj >> 1];
        }
    }
}

// ============================================================================
// Fused FiLM GEMM: computes gamma rows (m0..m0+127) and beta rows (256+m0..)
// of w_film @ y + b_film, then writes out = (x*gamma + beta) * xmask directly.
// 512 threads, 128x128 tile, double-buffered, dynamic smem 52224 B.
// ============================================================================
#define FILM_SMEM ((3 * 2 * 16 * SA) * 4)

__global__ __launch_bounds__(512)
void film_gemm(const float* __restrict__ Wf, const float* __restrict__ Yin,
               const float* __restrict__ bfilm, const float* __restrict__ x,
               const float* __restrict__ xmask, float* __restrict__ out)
{
    extern __shared__ uint32_t smf[];
    uint32_t* AsG = smf;                    // [2][16*SA]
    uint32_t* AsB = smf + 2 * 16 * SA;
    uint32_t* Bs  = smf + 4 * 16 * SA;

    const int tid = threadIdx.x;
    const int bz  = blockIdx.z;
    const float* Bb = Yin + (size_t)bz * CH * TT;
    const int m0 = blockIdx.y * 128, n0 = blockIdx.x * 128;

    const int wid = tid >> 5, lane = tid & 31;
    const int wm = wid >> 2, wn = wid & 3;
    const int r = lane >> 2, c = lane & 3;

    const int l_row = tid >> 5;
    const int l_col = lane * 4;
    const int l_am  = tid >> 2;
    const int l_ak  = (tid & 3) * 4;

    float acc_g[2][4][4] = {};
    float acc_b[2][4][4] = {};

#define LOAD_TILE_F(k0, buf)                                                            \
    {                                                                                   \
        float4 bv = *(const float4*)&Bb[(size_t)((k0) + l_row) * TT + n0 + l_col];      \
        uint4 bu; bu.x = f2tf(bv.x); bu.y = f2tf(bv.y); bu.z = f2tf(bv.z); bu.w = f2tf(bv.w); \
        *(uint4*)&Bs[(buf) * 16 * SA + l_row * SA + l_col] = bu;                        \
        float4 ag = *(const float4*)&Wf[(size_t)(m0 + l_am) * CH + (k0) + l_ak];        \
        AsG[(buf) * 16 * SA + (l_ak + 0) * SA + l_am] = f2tf(ag.x);                     \
        AsG[(buf) * 16 * SA + (l_ak + 1) * SA + l_am] = f2tf(ag.y);                     \
        AsG[(buf) * 16 * SA + (l_ak + 2) * SA + l_am] = f2tf(ag.z);                     \
        AsG[(buf) * 16 * SA + (l_ak + 3) * SA + l_am] = f2tf(ag.w);                     \
        float4 ab = *(const float4*)&Wf[(size_t)(256 + m0 + l_am) * CH + (k0) + l_ak];  \
        AsB[(buf) * 16 * SA + (l_ak + 0) * SA + l_am] = f2tf(ab.x);                     \
        AsB[(buf) * 16 * SA + (l_ak + 1) * SA + l_am] = f2tf(ab.y);                     \
        AsB[(buf) * 16 * SA + (l_ak + 2) * SA + l_am] = f2tf(ab.z);                     \
        AsB[(buf) * 16 * SA + (l_ak + 3) * SA + l_am] = f2tf(ab.w);                     \
    }

    LOAD_TILE_F(0, 0);
    __syncthreads();

    const int nk = CH / 16;   // 16
    for (int kb = 0; kb < nk; ++kb) {
        const int cur = kb & 1;
        if (kb + 1 < nk) LOAD_TILE_F((kb + 1) * 16, cur ^ 1);

#pragma unroll
        for (int k8 = 0; k8 < 16; k8 += 8) {
            uint32_t afg[2][4], afb[2][4], bf[4][2];
#pragma unroll
            for (int mt = 0; mt < 2; ++mt) {
                int mbx = wm * 32 + mt * 16 + r;
                afg[mt][0] = AsG[cur * 16 * SA + (k8 + c) * SA + mbx];
                afg[mt][1] = AsG[cur * 16 * SA + (k8 + c) * SA + mbx + 8];
                afg[mt][2] = AsG[cur * 16 * SA + (k8 + c + 4) * SA + mbx];
                afg[mt][3] = AsG[cur * 16 * SA + (k8 + c + 4) * SA + mbx + 8];
                afb[mt][0] = AsB[cur * 16 * SA + (k8 + c) * SA + mbx];
                afb[mt][1] = AsB[cur * 16 * SA + (k8 + c) * SA + mbx + 8];
                afb[mt][2] = AsB[cur * 16 * SA + (k8 + c + 4) * SA + mbx];
                afb[mt][3] = AsB[cur * 16 * SA + (k8 + c + 4) * SA + mbx + 8];
            }
#pragma unroll
            for (int nt = 0; nt < 4; ++nt) {
                int nb = wn * 32 + nt * 8 + r;
                bf[nt][0] = Bs[cur * 16 * SA + (k8 + c) * SA + nb];
                bf[nt][1] = Bs[cur * 16 * SA + (k8 + c + 4) * SA + nb];
            }
#pragma unroll
            for (int mt = 0; mt < 2; ++mt)
#pragma unroll
                for (int nt = 0; nt < 4; ++nt) {
                    mma_tf32(acc_g[mt][nt], afg[mt], bf[nt]);
                    mma_tf32(acc_b[mt][nt], afb[mt], bf[nt]);
                }
        }
        __syncthreads();
    }
#undef LOAD_TILE_F

    // epilogue: out = (x * gamma + beta) * xmask
#pragma unroll
    for (int mt = 0; mt < 2; ++mt) {
#pragma unroll
        for (int h = 0; h < 2; ++h) {
            const int row = m0 + wm * 32 + mt * 16 + r + h * 8;   // channel 0..255
            float bg = bfilm[row];
            float bb = bfilm[256 + row];
#pragma unroll
            for (int nt = 0; nt < 4; ++nt) {
                const int col = n0 + wn * 32 + nt * 8 + c * 2;
                float g0  = acc_g[mt][nt][h * 2 + 0] + bg;
                float g1  = acc_g[mt][nt][h * 2 + 1] + bg;
                float be0 = acc_b[mt][nt][h * 2 + 0] + bb;
                float be1 = acc_b[mt][nt][h * 2 + 1] + bb;
                float2 xv = *(const float2*)&x[((size_t)bz * CH + row) * TT + col];
                float xmm0 = xmask[(size_t)bz * TT + col];
                float xmm1 = xmask[(size_t)bz * TT + col + 1];
                float2 o;
                o.x = (xv.x * g0 + be0) * xmm0;
                o.y = (xv.y * g1 + be1) * xmm1;
                *(float2*)&out[((size_t)bz * CH + row) * TT + col] = o;
            }
        }
    }
}

// ---------------- launch ----------------
extern "C" void kernel_launch(void* const* d_in, const int* in_sizes, int n_in,
                              void* d_out, int out_size) {
    const float* x           = (const float*)d_in[0];
    const float* x_mask      = (const float*)d_in[1];
    const float* cond_latent = (const float*)d_in[2];
    const float* cond_mask   = (const float*)d_in[3];
    const float* w_cond      = (const float*)d_in[4];
    const float* b_cond      = (const float*)d_in[5];
    const float* wq          = (const float*)d_in[6];
    const float* bq          = (const float*)d_in[7];
    const float* wk          = (const float*)d_in[8];
    const float* bk          = (const float*)d_in[9];
    const float* wv          = (const float*)d_in[10];
    const float* bv          = (const float*)d_in[11];
    const float* wo          = (const float*)d_in[12];
    const float* bo          = (const float*)d_in[13];
    const float* w_film      = (const float*)d_in[14];
    const float* b_film      = (const float*)d_in[15];
    float* out = (float*)d_out;

    float *p_c, *p_q, *p_k, *p_v, *p_att, *p_y;
    cudaGetSymbolAddress((void**)&p_c,   g_c);
    cudaGetSymbolAddress((void**)&p_q,   g_q);
    cudaGetSymbolAddress((void**)&p_k,   g_k);
    cudaGetSymbolAddress((void**)&p_v,   g_v);
    cudaGetSymbolAddress((void**)&p_att, g_att);
    cudaGetSymbolAddress((void**)&p_y,   g_y);

    cudaFuncSetAttribute(flash_attn, cudaFuncAttributeMaxDynamicSharedMemorySize, FLASH_SMEM);
    cudaFuncSetAttribute(film_gemm,  cudaFuncAttributeMaxDynamicSharedMemorySize, FILM_SMEM);

    // RoPE tables [d][t]
    rope_table_kernel<<<(32 * TT + 255) / 256, 256>>>();

    // c = w_cond @ cond_latent + b_cond     [b][256][512]
    mma_gemm128<1, 0><<<dim3(TSL / 128, CH / 128, BQ), 512>>>(
        w_cond, cond_latent, b_cond, nullptr, p_c,
        CH, TSL, CONDC, 0, (size_t)CONDC * TSL, (size_t)CH * TSL);

    // q = wq @ x + bq                        [b][256][2048]
    mma_gemm128<1, 0><<<dim3(TT / 128, CH / 128, BQ), 512>>>(
        wq, x, bq, nullptr, p_q,
        CH, TT, CH, 0, (size_t)CH * TT, (size_t)CH * TT);

    // k = wk @ c + bk ; v = wv @ c + bv      [b][256][512]
    mma_gemm128<1, 0><<<dim3(TSL / 128, CH / 128, BQ), 512>>>(
        wk, p_c, bk, nullptr, p_k,
        CH, TSL, CH, 0, (size_t)CH * TSL, (size_t)CH * TSL);
    mma_gemm128<1, 0><<<dim3(TSL / 128, CH / 128, BQ), 512>>>(
        wv, p_c, bv, nullptr, p_v,
        CH, TSL, CH, 0, (size_t)CH * TSL, (size_t)CH * TSL);

    // fused attention (rope + scores + mask + softmax + P@V)
    flash_attn<<<dim3(1, TT / 128, BQ * NH), 256, FLASH_SMEM>>>(
        p_q, p_k, p_v, x_mask, cond_mask, p_att);

    // y = wo @ att + bo
    mma_gemm128<1, 0><<<dim3(TT / 128, CH / 128, BQ), 512>>>(
        wo, p_att, bo, nullptr, p_y,
        CH, TT, CH, 0, (size_t)CH * TT, (size_t)CH * TT);

    // fused FiLM: out = (x * (Wf@y+bf)[:256] + (Wf@y+bf)[256:]) * xmask
    film_gemm<<<dim3(TT / 128, CH / 128, BQ), 512, FILM_SMEM>>>(
        w_film, p_y, b_film, x, x_mask, out);
}

// round 4
// speedup vs baseline: 2.7267x; 1.0695x over previous
#include <cuda_runtime.h>
#include <math.h>
#include <stdint.h>

// ---------------- problem constants (fixed shapes) ----------------
#define BQ   16      // batch
#define CH   256     // hidden
#define CONDC 512    // cond channels
#define TT   2048    // target length
#define TSL  512     // source length
#define NH   4       // heads
#define KC   64      // head dim

#define SA 136       // padded smem stride (words): mod 32 = 8 (CF fragment loads), *4 % 16 == 0

// ---------------- scratch (device globals; no allocation) ----------------
__device__ float g_c  [BQ * CH * TSL];        // cond proj           [b][C][Ts]
__device__ float g_q  [BQ * CH * TT];         // q (un-roped)        [bh][64][Tt]
__device__ float g_k  [BQ * CH * TSL];        // k (roped+masked)    [bh][64][Ts]
__device__ float g_v  [BQ * CH * TSL];        // v                   [bh][64][Ts]
__device__ float g_att[BQ * CH * TT];         // attn out            [b][C][Tt]
__device__ float g_y  [BQ * CH * TT];         // wo proj             [b][C][Tt]
__device__ float g_cos[32 * TT];              // [d][t]
__device__ float g_sin[32 * TT];

// ---------------- tf32 helpers ----------------
__device__ __forceinline__ uint32_t f2tf(float f) {
    uint32_t u;
    asm("cvt.rna.tf32.f32 %0, %1;" : "=r"(u) : "f"(f));
    return u;
}

__device__ __forceinline__ void mma_tf32(float* c, const uint32_t* a, const uint32_t* b) {
    asm volatile(
        "mma.sync.aligned.m16n8k8.row.col.f32.tf32.tf32.f32 "
        "{%0,%1,%2,%3}, {%4,%5,%6,%7}, {%8,%9}, {%0,%1,%2,%3};\n"
        : "+f"(c[0]), "+f"(c[1]), "+f"(c[2]), "+f"(c[3])
        : "r"(a[0]), "r"(a[1]), "r"(a[2]), "r"(a[3]), "r"(b[0]), "r"(b[1]));
}

// ---------------- RoPE tables, layout [d][t] ----------------
__global__ void rope_table_kernel() {
    int idx = blockIdx.x * blockDim.x + threadIdx.x;
    if (idx >= 32 * TT) return;
    int d = idx / TT;
    int t = idx % TT;
    float invf = (float)pow(10000.0, -(double)d / 32.0);
    float ang  = (float)t * invf;            // same fp32 rounding as reference
    g_cos[idx] = (float)cos((double)ang);
    g_sin[idx] = (float)sin((double)ang);
}

// ---------------- pre-rope + mask K in place: [bh][64][Ts] ----------------
__global__ void rope_k_mask_kernel(float* __restrict__ k, const float* __restrict__ cmask) {
    int idx = blockIdx.x * blockDim.x + threadIdx.x;
    if (idx >= BQ * NH * 32 * TSL) return;
    int t  = idx & (TSL - 1);
    int rr = idx >> 9;            // TSL = 512
    int d  = rr & 31;
    int bh = rr >> 5;
    int b  = bh >> 2;
    float cs = g_cos[d * TT + t];
    float sn = g_sin[d * TT + t];
    float cm = cmask[(size_t)b * TSL + t];
    size_t base = ((size_t)bh * KC + d) * TSL + t;
    float k1 = k[base];
    float k2 = k[base + (size_t)32 * TSL];
    k[base]                    = (k1 * cs - k2 * sn) * cm;
    k[base + (size_t)32 * TSL] = (k2 * cs + k1 * sn) * cm;
}

// ============================================================================
// Generic tf32 MMA GEMM, 128x128 CTA tile, 512 threads, BK=16, double-buffered.
// A stored [M][K] global -> transpose-on-load. Y = A@B + bias[m].
// ============================================================================
__global__ __launch_bounds__(512)
void mma_gemm128(const float* __restrict__ A, const float* __restrict__ B,
                 const float* __restrict__ bias, float* __restrict__ Y,
                 int Ndim, int Kdim, size_t strideB, size_t strideY)
{
    __shared__ uint32_t As[2][16 * SA];
    __shared__ uint32_t Bs[2][16 * SA];

    const int tid = threadIdx.x;
    const int bz  = blockIdx.z;
    const float* Bb = B + (size_t)bz * strideB;
    float*       Yb = Y + (size_t)bz * strideY;
    const int m0 = blockIdx.y * 128, n0 = blockIdx.x * 128;

    const int wid = tid >> 5, lane = tid & 31;
    const int wm = wid >> 2, wn = wid & 3;
    const int r = lane >> 2, c = lane & 3;

    const int l_row  = tid >> 5;
    const int l_col  = lane * 4;
    const int l_am   = tid >> 2;
    const int l_ak   = (tid & 3) * 4;

    float acc[2][4][4] = {};
    const int nk = Kdim / 16;

#define LOAD_TILE(k0, buf)                                                              \
    {                                                                                   \
        float4 bv = *(const float4*)&Bb[(size_t)((k0) + l_row) * Ndim + n0 + l_col];    \
        uint4 bu; bu.x = f2tf(bv.x); bu.y = f2tf(bv.y); bu.z = f2tf(bv.z); bu.w = f2tf(bv.w); \
        *(uint4*)&Bs[buf][l_row * SA + l_col] = bu;                                     \
        float4 av = *(const float4*)&A[(size_t)(m0 + l_am) * Kdim + (k0) + l_ak];       \
        As[buf][(l_ak + 0) * SA + l_am] = f2tf(av.x);                                   \
        As[buf][(l_ak + 1) * SA + l_am] = f2tf(av.y);                                   \
        As[buf][(l_ak + 2) * SA + l_am] = f2tf(av.z);                                   \
        As[buf][(l_ak + 3) * SA + l_am] = f2tf(av.w);                                   \
    }

    LOAD_TILE(0, 0);
    __syncthreads();

    for (int kb = 0; kb < nk; ++kb) {
        const int cur = kb & 1;
        if (kb + 1 < nk) LOAD_TILE((kb + 1) * 16, cur ^ 1);

#pragma unroll
        for (int k8 = 0; k8 < 16; k8 += 8) {
            uint32_t af[2][4], bf[4][2];
#pragma unroll
            for (int mt = 0; mt < 2; ++mt) {
                int mb = wm * 32 + mt * 16 + r;
                af[mt][0] = As[cur][(k8 + c) * SA + mb];
                af[mt][1] = As[cur][(k8 + c) * SA + mb + 8];
                af[mt][2] = As[cur][(k8 + c + 4) * SA + mb];
                af[mt][3] = As[cur][(k8 + c + 4) * SA + mb + 8];
            }
#pragma unroll
            for (int nt = 0; nt < 4; ++nt) {
                int nb = wn * 32 + nt * 8 + r;
                bf[nt][0] = Bs[cur][(k8 + c) * SA + nb];
                bf[nt][1] = Bs[cur][(k8 + c + 4) * SA + nb];
            }
#pragma unroll
            for (int mt = 0; mt < 2; ++mt)
#pragma unroll
                for (int nt = 0; nt < 4; ++nt)
                    mma_tf32(acc[mt][nt], af[mt], bf[nt]);
        }
        __syncthreads();
    }

#pragma unroll
    for (int mt = 0; mt < 2; ++mt) {
#pragma unroll
        for (int h = 0; h < 2; ++h) {
            const int row = m0 + wm * 32 + mt * 16 + r + h * 8;
            float bval = bias[row];
#pragma unroll
            for (int nt = 0; nt < 4; ++nt) {
                const int col = n0 + wn * 32 + nt * 8 + c * 2;
                float2 o;
                o.x = acc[mt][nt][h * 2 + 0] + bval;
                o.y = acc[mt][nt][h * 2 + 1] + bval;
                *(float2*)&Yb[(size_t)row * Ndim + col] = o;
            }
        }
    }
}

// Same kernel, but fused k+v: grid.z = 32; z<16 -> (wk,bk,g_k), else (wv,bv,g_v).
__global__ __launch_bounds__(512)
void mma_gemm128_kv(const float* __restrict__ Wk, const float* __restrict__ Wv,
                    const float* __restrict__ B,
                    const float* __restrict__ bk, const float* __restrict__ bv,
                    float* __restrict__ Yk, float* __restrict__ Yv)
{
    __shared__ uint32_t As[2][16 * SA];
    __shared__ uint32_t Bs[2][16 * SA];

    const int tid = threadIdx.x;
    const int zz  = blockIdx.z;
    const int bz  = zz & 15;
    const int sel = zz >> 4;
    const float* A    = sel ? Wv : Wk;
    const float* bias = sel ? bv : bk;
    float*       Y    = sel ? Yv : Yk;
    const float* Bb = B + (size_t)bz * CH * TSL;
    float*       Yb = Y + (size_t)bz * CH * TSL;
    const int m0 = blockIdx.y * 128, n0 = blockIdx.x * 128;

    const int wid = tid >> 5, lane = tid & 31;
    const int wm = wid >> 2, wn = wid & 3;
    const int r = lane >> 2, c = lane & 3;

    const int l_row  = tid >> 5;
    const int l_col  = lane * 4;
    const int l_am   = tid >> 2;
    const int l_ak   = (tid & 3) * 4;

    float acc[2][4][4] = {};
    const int nk = CH / 16;

#define LOAD_TILE_KV(k0, buf)                                                           \
    {                                                                                   \
        float4 bvv = *(const float4*)&Bb[(size_t)((k0) + l_row) * TSL + n0 + l_col];    \
        uint4 bu; bu.x = f2tf(bvv.x); bu.y = f2tf(bvv.y); bu.z = f2tf(bvv.z); bu.w = f2tf(bvv.w); \
        *(uint4*)&Bs[buf][l_row * SA + l_col] = bu;                                     \
        float4 av = *(const float4*)&A[(size_t)(m0 + l_am) * CH + (k0) + l_ak];         \
        As[buf][(l_ak + 0) * SA + l_am] = f2tf(av.x);                                   \
        As[buf][(l_ak + 1) * SA + l_am] = f2tf(av.y);                                   \
        As[buf][(l_ak + 2) * SA + l_am] = f2tf(av.z);                                   \
        As[buf][(l_ak + 3) * SA + l_am] = f2tf(av.w);                                   \
    }

    LOAD_TILE_KV(0, 0);
    __syncthreads();

    for (int kb = 0; kb < nk; ++kb) {
        const int cur = kb & 1;
        if (kb + 1 < nk) LOAD_TILE_KV((kb + 1) * 16, cur ^ 1);

#pragma unroll
        for (int k8 = 0; k8 < 16; k8 += 8) {
            uint32_t af[2][4], bf[4][2];
#pragma unroll
            for (int mt = 0; mt < 2; ++mt) {
                int mb = wm * 32 + mt * 16 + r;
                af[mt][0] = As[cur][(k8 + c) * SA + mb];
                af[mt][1] = As[cur][(k8 + c) * SA + mb + 8];
                af[mt][2] = As[cur][(k8 + c + 4) * SA + mb];
                af[mt][3] = As[cur][(k8 + c + 4) * SA + mb + 8];
            }
#pragma unroll
            for (int nt = 0; nt < 4; ++nt) {
                int nb = wn * 32 + nt * 8 + r;
                bf[nt][0] = Bs[cur][(k8 + c) * SA + nb];
                bf[nt][1] = Bs[cur][(k8 + c + 4) * SA + nb];
            }
#pragma unroll
            for (int mt = 0; mt < 2; ++mt)
#pragma unroll
                for (int nt = 0; nt < 4; ++nt)
                    mma_tf32(acc[mt][nt], af[mt], bf[nt]);
        }
        __syncthreads();
    }

#pragma unroll
    for (int mt = 0; mt < 2; ++mt) {
#pragma unroll
        for (int h = 0; h < 2; ++h) {
            const int row = m0 + wm * 32 + mt * 16 + r + h * 8;
            float bval = bias[row];
#pragma unroll
            for (int nt = 0; nt < 4; ++nt) {
                const int col = n0 + wn * 32 + nt * 8 + c * 2;
                float2 o;
                o.x = acc[mt][nt][h * 2 + 0] + bval;
                o.y = acc[mt][nt][h * 2 + 1] + bval;
                *(float2*)&Yb[(size_t)row * TSL + col] = o;
            }
        }
    }
}

// ============================================================================
// Fused flash attention v2 (tf32 MMA). K pre-roped+masked, cmask bias in smem,
// register-carried prefetch of K/V chunks, coalesced transposed epilogue.
// Per CTA: (bh, m-tile of 128 q rows). 256 threads = 8 warps x 16 rows.
// smem: Qs[64][136] | Ks[64][72] | Vs[64][68] | Ps[64][136] | cmb[512]
// ============================================================================
#define FSA 136
#define FSK 72
#define FSV 68
#define FLASH_SMEM ((64*FSA + 64*FSK + 64*FSV + 64*FSA + 512) * 4)

__global__ __launch_bounds__(256, 2)
void flash_attn(const float* __restrict__ Qg, const float* __restrict__ Kg,
                const float* __restrict__ Vg, const float* __restrict__ cmask,
                float* __restrict__ O)
{
    extern __shared__ uint32_t sm[];
    uint32_t* Qs  = sm;                    // [64][136]
    uint32_t* Ks  = sm + 64 * FSA;         // [64][72]   [d][n]
    uint32_t* Vs  = Ks + 64 * FSK;         // [64][68]   [ch][pos]
    uint32_t* Ps  = Vs + 64 * FSV;         // [64][136]  [k][m] / f32 [n][m] epilogue
    float*    cmb = (float*)(Ps + 64 * FSA);  // [512] additive bias

    const int bh = blockIdx.z;
    const int b  = bh >> 2;
    const int m0 = blockIdx.y * 128;
    const int tid = threadIdx.x, wid = tid >> 5, lane = tid & 31;
    const int r = lane >> 2, c = lane & 3;
    const int mb = wid * 16 + r;

    const float* Qb = Qg + (size_t)bh * KC * TT;
    const float* Kb = Kg + (size_t)bh * KC * TSL;
    const float* Vb = Vg + (size_t)bh * KC * TSL;

    // ---- load Q tile (64 x 128) with RoPE ----
    {
        int d  = tid >> 3;          // 0..31
        int mg = (tid & 7) * 16;
#pragma unroll
        for (int j = 0; j < 16; j += 4) {
            int m = mg + j;
            int t = m0 + m;
            float4 q1 = *(const float4*)&Qb[(size_t)d * TT + t];
            float4 q2 = *(const float4*)&Qb[(size_t)(d + 32) * TT + t];
            float4 cv = *(const float4*)&g_cos[(size_t)d * TT + t];
            float4 sv = *(const float4*)&g_sin[(size_t)d * TT + t];
            Qs[d * FSA + m + 0] = f2tf(q1.x * cv.x - q2.x * sv.x);
            Qs[d * FSA + m + 1] = f2tf(q1.y * cv.y - q2.y * sv.y);
            Qs[d * FSA + m + 2] = f2tf(q1.z * cv.z - q2.z * sv.z);
            Qs[d * FSA + m + 3] = f2tf(q1.w * cv.w - q2.w * sv.w);
            Qs[(d + 32) * FSA + m + 0] = f2tf(q2.x * cv.x + q1.x * sv.x);
            Qs[(d + 32) * FSA + m + 1] = f2tf(q2.y * cv.y + q1.y * sv.y);
            Qs[(d + 32) * FSA + m + 2] = f2tf(q2.z * cv.z + q1.z * sv.z);
            Qs[(d + 32) * FSA + m + 3] = f2tf(q2.w * cv.w + q1.w * sv.w);
        }
    }
    // ---- cmask -> additive bias in smem ----
    for (int i = tid; i < TSL; i += 256)
        cmb[i] = (cmask[(size_t)b * TSL + i] == 0.f) ? -1e4f : 0.f;

    // ---- prefetch chunk 0 into registers ----
    const int prow = tid >> 2;          // 0..63
    const int pcol = (tid & 3) * 4;     // col = pcol + 16*j
    float4 kr[4], vr[4];
#pragma unroll
    for (int j = 0; j < 4; ++j) {
        kr[j] = *(const float4*)&Kb[(size_t)prow * TSL + pcol + 16 * j];
        vr[j] = *(const float4*)&Vb[(size_t)prow * TSL + pcol + 16 * j];
    }

    float m_run[2] = {-1e30f, -1e30f};
    float l_run[2] = {0.f, 0.f};
    float acc_o[8][4] = {};

    __syncthreads();   // Qs + cmb visible

    for (int ci = 0; ci < 8; ++ci) {
        const int s0 = ci * 64;
        // ---- store prefetched K/V into smem (tf32) ----
#pragma unroll
        for (int j = 0; j < 4; ++j) {
            int col = pcol + 16 * j;
            Ks[prow * FSK + col + 0] = f2tf(kr[j].x);
            Ks[prow * FSK + col + 1] = f2tf(kr[j].y);
            Ks[prow * FSK + col + 2] = f2tf(kr[j].z);
            Ks[prow * FSK + col + 3] = f2tf(kr[j].w);
            Vs[prow * FSV + col + 0] = f2tf(vr[j].x);
            Vs[prow * FSV + col + 1] = f2tf(vr[j].y);
            Vs[prow * FSV + col + 2] = f2tf(vr[j].z);
            Vs[prow * FSV + col + 3] = f2tf(vr[j].w);
        }
        __syncthreads();
        // ---- prefetch next chunk (latency hidden behind compute below) ----
        if (ci < 7) {
#pragma unroll
            for (int j = 0; j < 4; ++j) {
                kr[j] = *(const float4*)&Kb[(size_t)prow * TSL + s0 + 64 + pcol + 16 * j];
                vr[j] = *(const float4*)&Vb[(size_t)prow * TSL + s0 + 64 + pcol + 16 * j];
            }
        }

        // ---- S = Q^T K : warp tile 16 x 64 ----
        float acc_s[8][4] = {};
#pragma unroll
        for (int k8 = 0; k8 < 64; k8 += 8) {
            uint32_t af[4];
            af[0] = Qs[(k8 + c) * FSA + mb];
            af[1] = Qs[(k8 + c) * FSA + mb + 8];
            af[2] = Qs[(k8 + c + 4) * FSA + mb];
            af[3] = Qs[(k8 + c + 4) * FSA + mb + 8];
#pragma unroll
            for (int nt = 0; nt < 8; ++nt) {
                uint32_t bf[2];
                bf[0] = Ks[(k8 + c) * FSK + nt * 8 + r];
                bf[1] = Ks[(k8 + c + 4) * FSK + nt * 8 + r];
                mma_tf32(acc_s[nt], af, bf);
            }
        }

        // ---- scale + bias + online softmax (warp-local rows) ----
        float mx[2] = {-1e30f, -1e30f};
#pragma unroll
        for (int nt = 0; nt < 8; ++nt) {
            float2 bias = *(float2*)&cmb[s0 + nt * 8 + 2 * c];
#pragma unroll
            for (int jj = 0; jj < 4; ++jj) {
                float v = acc_s[nt][jj] * 0.125f + ((jj & 1) ? bias.y : bias.x);
                acc_s[nt][jj] = v;
                mx[jj >> 1] = fmaxf(mx[jj >> 1], v);
            }
        }
#pragma unroll
        for (int h = 0; h < 2; ++h) {
            mx[h] = fmaxf(mx[h], __shfl_xor_sync(0xffffffffu, mx[h], 1));
            mx[h] = fmaxf(mx[h], __shfl_xor_sync(0xffffffffu, mx[h], 2));
        }
        float mnew[2], scale[2], lad[2] = {0.f, 0.f};
#pragma unroll
        for (int h = 0; h < 2; ++h) {
            mnew[h]  = fmaxf(m_run[h], mx[h]);
            scale[h] = __expf(m_run[h] - mnew[h]);
            m_run[h] = mnew[h];
        }
#pragma unroll
        for (int nt = 0; nt < 8; ++nt) {
#pragma unroll
            for (int jj = 0; jj < 4; ++jj) {
                float e = __expf(acc_s[nt][jj] - mnew[jj >> 1]);
                acc_s[nt][jj] = e;
                lad[jj >> 1] += e;
            }
        }
#pragma unroll
        for (int h = 0; h < 2; ++h) {
            lad[h] += __shfl_xor_sync(0xffffffffu, lad[h], 1);
            lad[h] += __shfl_xor_sync(0xffffffffu, lad[h], 2);
            l_run[h] = l_run[h] * scale[h] + lad[h];
        }
#pragma unroll
        for (int nt = 0; nt < 8; ++nt) {
#pragma unroll
            for (int jj = 0; jj < 4; ++jj)
                acc_o[nt][jj] *= scale[jj >> 1];
        }
        // P -> smem [k][m] (warp-private m-stripe)
#pragma unroll
        for (int nt = 0; nt < 8; ++nt) {
#pragma unroll
            for (int jj = 0; jj < 4; ++jj) {
                int kcol = nt * 8 + 2 * c + (jj & 1);
                int mrow = wid * 16 + r + (jj >> 1) * 8;
                Ps[kcol * FSA + mrow] = f2tf(acc_s[nt][jj]);
            }
        }
        __syncwarp();

        // ---- O += P @ V^T ----
#pragma unroll
        for (int k8 = 0; k8 < 64; k8 += 8) {
            uint32_t af[4];
            af[0] = Ps[(k8 + c) * FSA + mb];
            af[1] = Ps[(k8 + c) * FSA + mb + 8];
            af[2] = Ps[(k8 + c + 4) * FSA + mb];
            af[3] = Ps[(k8 + c + 4) * FSA + mb + 8];
#pragma unroll
            for (int nt = 0; nt < 8; ++nt) {
                uint32_t bf[2];
                bf[0] = Vs[(nt * 8 + r) * FSV + k8 + c];
                bf[1] = Vs[(nt * 8 + r) * FSV + k8 + c + 4];
                mma_tf32(acc_o[nt], af, bf);
            }
        }
        __syncthreads();   // smem reads done before next chunk's stores
    }

    // ---- epilogue: /l, transpose via smem, coalesced store ----
    float inv[2] = {1.f / l_run[0], 1.f / l_run[1]};
    float* Pf = (float*)Ps;
#pragma unroll
    for (int nt = 0; nt < 8; ++nt) {
#pragma unroll
        for (int jj = 0; jj < 4; ++jj) {
            int n = nt * 8 + 2 * c + (jj & 1);
            int m = wid * 16 + r + (jj >> 1) * 8;
            Pf[n * FSA + m] = acc_o[nt][jj] * inv[jj >> 1];
        }
    }
    __syncthreads();
    {
        int row = tid >> 2;          // 0..63 (output channel)
        int mq  = (tid & 3) * 4;
#pragma unroll
        for (int j = 0; j < 8; ++j) {
            int m = mq + 16 * j;
            *(float4*)&O[((size_t)bh * KC + row) * TT + m0 + m] =
                *(float4*)&Pf[row * FSA + m];
        }
    }
}

// ============================================================================
// Fused FiLM GEMM (unchanged from R3)
// ============================================================================
#define FILM_SMEM ((3 * 2 * 16 * SA) * 4)

__global__ __launch_bounds__(512)
void film_gemm(const float* __restrict__ Wf, const float* __restrict__ Yin,
               const float* __restrict__ bfilm, const float* __restrict__ x,
               const float* __restrict__ xmask, float* __restrict__ out)
{
    extern __shared__ uint32_t smf[];
    uint32_t* AsG = smf;
    uint32_t* AsB = smf + 2 * 16 * SA;
    uint32_t* Bs  = smf + 4 * 16 * SA;

    const int tid = threadIdx.x;
    const int bz  = blockIdx.z;
    const float* Bb = Yin + (size_t)bz * CH * TT;
    const int m0 = blockIdx.y * 128, n0 = blockIdx.x * 128;

    const int wid = tid >> 5, lane = tid & 31;
    const int wm = wid >> 2, wn = wid & 3;
    const int r = lane >> 2, c = lane & 3;

    const int l_row = tid >> 5;
    const int l_col = lane * 4;
    const int l_am  = tid >> 2;
    const int l_ak  = (tid & 3) * 4;

    float acc_g[2][4][4] = {};
    float acc_b[2][4][4] = {};

#define LOAD_TILE_F(k0, buf)                                                            \
    {                                                                                   \
        float4 bv = *(const float4*)&Bb[(size_t)((k0) + l_row) * TT + n0 + l_col];      \
        uint4 bu; bu.x = f2tf(bv.x); bu.y = f2tf(bv.y); bu.z = f2tf(bv.z); bu.w = f2tf(bv.w); \
        *(uint4*)&Bs[(buf) * 16 * SA + l_row * SA + l_col] = bu;                        \
        float4 ag = *(const float4*)&Wf[(size_t)(m0 + l_am) * CH + (k0) + l_ak];        \
        AsG[(buf) * 16 * SA + (l_ak + 0) * SA + l_am] = f2tf(ag.x);                     \
        AsG[(buf) * 16 * SA + (l_ak + 1) * SA + l_am] = f2tf(ag.y);                     \
        AsG[(buf) * 16 * SA + (l_ak + 2) * SA + l_am] = f2tf(ag.z);                     \
        AsG[(buf) * 16 * SA + (l_ak + 3) * SA + l_am] = f2tf(ag.w);                     \
        float4 ab = *(const float4*)&Wf[(size_t)(256 + m0 + l_am) * CH + (k0) + l_ak];  \
        AsB[(buf) * 16 * SA + (l_ak + 0) * SA + l_am] = f2tf(ab.x);                     \
        AsB[(buf) * 16 * SA + (l_ak + 1) * SA + l_am] = f2tf(ab.y);                     \
        AsB[(buf) * 16 * SA + (l_ak + 2) * SA + l_am] = f2tf(ab.z);                     \
        AsB[(buf) * 16 * SA + (l_ak + 3) * SA + l_am] = f2tf(ab.w);                     \
    }

    LOAD_TILE_F(0, 0);
    __syncthreads();

    const int nk = CH / 16;
    for (int kb = 0; kb < nk; ++kb) {
        const int cur = kb & 1;
        if (kb + 1 < nk) LOAD_TILE_F((kb + 1) * 16, cur ^ 1);

#pragma unroll
        for (int k8 = 0; k8 < 16; k8 += 8) {
            uint32_t afg[2][4], afb[2][4], bf[4][2];
#pragma unroll
            for (int mt = 0; mt < 2; ++mt) {
                int mbx = wm * 32 + mt * 16 + r;
                afg[mt][0] = AsG[cur * 16 * SA + (k8 + c) * SA + mbx];
                afg[mt][1] = AsG[cur * 16 * SA + (k8 + c) * SA + mbx + 8];
                afg[mt][2] = AsG[cur * 16 * SA + (k8 + c + 4) * SA + mbx];
                afg[mt][3] = AsG[cur * 16 * SA + (k8 + c + 4) * SA + mbx + 8];
                afb[mt][0] = AsB[cur * 16 * SA + (k8 + c) * SA + mbx];
                afb[mt][1] = AsB[cur * 16 * SA + (k8 + c) * SA + mbx + 8];
                afb[mt][2] = AsB[cur * 16 * SA + (k8 + c + 4) * SA + mbx];
                afb[mt][3] = AsB[cur * 16 * SA + (k8 + c + 4) * SA + mbx + 8];
            }
#pragma unroll
            for (int nt = 0; nt < 4; ++nt) {
                int nb = wn * 32 + nt * 8 + r;
                bf[nt][0] = Bs[cur * 16 * SA + (k8 + c) * SA + nb];
                bf[nt][1] = Bs[cur * 16 * SA + (k8 + c + 4) * SA + nb];
            }
#pragma unroll
            for (int mt = 0; mt < 2; ++mt)
#pragma unroll
                for (int nt = 0; nt < 4; ++nt) {
                    mma_tf32(acc_g[mt][nt], afg[mt], bf[nt]);
                    mma_tf32(acc_b[mt][nt], afb[mt], bf[nt]);
                }
        }
        __syncthreads();
    }

#pragma unroll
    for (int mt = 0; mt < 2; ++mt) {
#pragma unroll
        for (int h = 0; h < 2; ++h) {
            const int row = m0 + wm * 32 + mt * 16 + r + h * 8;
            float bg = bfilm[row];
            float bb = bfilm[256 + row];
#pragma unroll
            for (int nt = 0; nt < 4; ++nt) {
                const int col = n0 + wn * 32 + nt * 8 + c * 2;
                float g0  = acc_g[mt][nt][h * 2 + 0] + bg;
                float g1  = acc_g[mt][nt][h * 2 + 1] + bg;
                float be0 = acc_b[mt][nt][h * 2 + 0] + bb;
                float be1 = acc_b[mt][nt][h * 2 + 1] + bb;
                float2 xv = *(const float2*)&x[((size_t)bz * CH + row) * TT + col];
                float xmm0 = xmask[(size_t)bz * TT + col];
                float xmm1 = xmask[(size_t)bz * TT + col + 1];
                float2 o;
                o.x = (xv.x * g0 + be0) * xmm0;
                o.y = (xv.y * g1 + be1) * xmm1;
                *(float2*)&out[((size_t)bz * CH + row) * TT + col] = o;
            }
        }
    }
}

// ---------------- launch ----------------
extern "C" void kernel_launch(void* const* d_in, const int* in_sizes, int n_in,
                              void* d_out, int out_size) {
    const float* x           = (const float*)d_in[0];
    const float* x_mask      = (const float*)d_in[1];
    const float* cond_latent = (const float*)d_in[2];
    const float* cond_mask   = (const float*)d_in[3];
    const float* w_cond      = (const float*)d_in[4];
    const float* b_cond      = (const float*)d_in[5];
    const float* wq          = (const float*)d_in[6];
    const float* bq          = (const float*)d_in[7];
    const float* wk          = (const float*)d_in[8];
    const float* bk          = (const float*)d_in[9];
    const float* wv          = (const float*)d_in[10];
    const float* bv          = (const float*)d_in[11];
    const float* wo          = (const float*)d_in[12];
    const float* bo          = (const float*)d_in[13];
    const float* w_film      = (const float*)d_in[14];
    const float* b_film      = (const float*)d_in[15];
    float* out = (float*)d_out;

    float *p_c, *p_q, *p_k, *p_v, *p_att, *p_y;
    cudaGetSymbolAddress((void**)&p_c,   g_c);
    cudaGetSymbolAddress((void**)&p_q,   g_q);
    cudaGetSymbolAddress((void**)&p_k,   g_k);
    cudaGetSymbolAddress((void**)&p_v,   g_v);
    cudaGetSymbolAddress((void**)&p_att, g_att);
    cudaGetSymbolAddress((void**)&p_y,   g_y);

    cudaFuncSetAttribute(flash_attn, cudaFuncAttributeMaxDynamicSharedMemorySize, FLASH_SMEM);
    cudaFuncSetAttribute(film_gemm,  cudaFuncAttributeMaxDynamicSharedMemorySize, FILM_SMEM);

    // RoPE tables [d][t]
    rope_table_kernel<<<(32 * TT + 255) / 256, 256>>>();

    // c = w_cond @ cond_latent + b_cond     [b][256][512]
    mma_gemm128<<<dim3(TSL / 128, CH / 128, BQ), 512>>>(
        w_cond, cond_latent, b_cond, p_c,
        TSL, CONDC, (size_t)CONDC * TSL, (size_t)CH * TSL);

    // q = wq @ x + bq                        [b][256][2048]
    mma_gemm128<<<dim3(TT / 128, CH / 128, BQ), 512>>>(
        wq, x, bq, p_q,
        TT, CH, (size_t)CH * TT, (size_t)CH * TT);

    // k and v fused in one launch (fills the chip)
    mma_gemm128_kv<<<dim3(TSL / 128, CH / 128, 2 * BQ), 512>>>(
        wk, wv, p_c, bk, bv, p_k, p_v);

    // pre-rope + cond-mask K in place
    rope_k_mask_kernel<<<(BQ * NH * 32 * TSL + 255) / 256, 256>>>(p_k, cond_mask);

    // fused attention (Q-rope + scores + bias-mask + softmax + P@V)
    flash_attn<<<dim3(1, TT / 128, BQ * NH), 256, FLASH_SMEM>>>(
        p_q, p_k, p_v, cond_mask, p_att);

    // y = wo @ att + bo
    mma_gemm128<<<dim3(TT / 128, CH / 128, BQ), 512>>>(
        wo, p_att, bo, p_y,
        TT, CH, (size_t)CH * TT, (size_t)CH * TT);

    // fused FiLM
    film_gemm<<<dim3(TT / 128, CH / 128, BQ), 512, FILM_SMEM>>>(
        w_film, p_y, b_film, x, x_mask, out);
}

// round 5
// speedup vs baseline: 2.7503x; 1.0087x over previous
#include <cuda_runtime.h>
#include <math.h>
#include <stdint.h>

// ---------------- problem constants (fixed shapes) ----------------
#define BQ   16      // batch
#define CH   256     // hidden
#define CONDC 512    // cond channels
#define TT   2048    // target length
#define TSL  512     // source length
#define NH   4       // heads
#define KC   64      // head dim

#define SA 136       // padded smem stride (words): mod 32 = 8 (CF fragment loads), *4 % 16 == 0

// ---------------- scratch (device globals; no allocation) ----------------
__device__ float g_c  [BQ * CH * TSL];        // cond proj           [b][C][Ts]
__device__ float g_q  [BQ * CH * TT];         // q (un-roped)        [bh][64][Tt]
__device__ float g_k  [BQ * CH * TSL];        // k (roped+masked)    [bh][64][Ts]
__device__ float g_v  [BQ * CH * TSL];        // v                   [bh][64][Ts]
__device__ float g_att[BQ * CH * TT];         // attn out            [b][C][Tt]
__device__ float g_y  [BQ * CH * TT];         // wo proj             [b][C][Tt]
__device__ float g_cos[32 * TT];              // [d][t]
__device__ float g_sin[32 * TT];

// ---------------- tf32 helpers ----------------
__device__ __forceinline__ uint32_t f2tf(float f) {
    uint32_t u;
    asm("cvt.rna.tf32.f32 %0, %1;" : "=r"(u) : "f"(f));
    return u;
}

__device__ __forceinline__ void mma_tf32(float* c, const uint32_t* a, const uint32_t* b) {
    asm volatile(
        "mma.sync.aligned.m16n8k8.row.col.f32.tf32.tf32.f32 "
        "{%0,%1,%2,%3}, {%4,%5,%6,%7}, {%8,%9}, {%0,%1,%2,%3};\n"
        : "+f"(c[0]), "+f"(c[1]), "+f"(c[2]), "+f"(c[3])
        : "r"(a[0]), "r"(a[1]), "r"(a[2]), "r"(a[3]), "r"(b[0]), "r"(b[1]));
}

// ---------------- RoPE tables, layout [d][t] ----------------
__global__ void rope_table_kernel() {
    int idx = blockIdx.x * blockDim.x + threadIdx.x;
    if (idx >= 32 * TT) return;
    int d = idx / TT;
    int t = idx % TT;
    float invf = (float)pow(10000.0, -(double)d / 32.0);
    float ang  = (float)t * invf;            // same fp32 rounding as reference
    g_cos[idx] = (float)cos((double)ang);
    g_sin[idx] = (float)sin((double)ang);
}

// ---------------- pre-rope + mask K in place: [bh][64][Ts] ----------------
__global__ void rope_k_mask_kernel(float* __restrict__ k, const float* __restrict__ cmask) {
    int idx = blockIdx.x * blockDim.x + threadIdx.x;
    if (idx >= BQ * NH * 32 * TSL) return;
    int t  = idx & (TSL - 1);
    int rr = idx >> 9;            // TSL = 512
    int d  = rr & 31;
    int bh = rr >> 5;
    int b  = bh >> 2;
    float cs = g_cos[d * TT + t];
    float sn = g_sin[d * TT + t];
    float cm = cmask[(size_t)b * TSL + t];
    size_t base = ((size_t)bh * KC + d) * TSL + t;
    float k1 = k[base];
    float k2 = k[base + (size_t)32 * TSL];
    k[base]                    = (k1 * cs - k2 * sn) * cm;
    k[base + (size_t)32 * TSL] = (k2 * cs + k1 * sn) * cm;
}

// ============================================================================
// Generic tf32 MMA GEMM, 128x128 CTA tile, 512 threads, BK=16, double-buffered
// with split LDG / compute / STS pipeline (global latency hidden behind MMAs).
// A stored [M][K] global -> transpose-on-load. Y = A@B + bias[m].
// ============================================================================
__global__ __launch_bounds__(512)
void mma_gemm128(const float* __restrict__ A, const float* __restrict__ B,
                 const float* __restrict__ bias, float* __restrict__ Y,
                 int Ndim, int Kdim, size_t strideB, size_t strideY)
{
    __shared__ uint32_t As[2][16 * SA];
    __shared__ uint32_t Bs[2][16 * SA];

    const int tid = threadIdx.x;
    const int bz  = blockIdx.z;
    const float* Bb = B + (size_t)bz * strideB;
    float*       Yb = Y + (size_t)bz * strideY;
    const int m0 = blockIdx.y * 128, n0 = blockIdx.x * 128;

    const int wid = tid >> 5, lane = tid & 31;
    const int wm = wid >> 2, wn = wid & 3;
    const int r = lane >> 2, c = lane & 3;

    const int l_row  = tid >> 5;
    const int l_col  = lane * 4;
    const int l_am   = tid >> 2;
    const int l_ak   = (tid & 3) * 4;

    float acc[2][4][4] = {};
    const int nk = Kdim / 16;

    float4 avr, bvr;
#define LDG_TILE(k0)                                                                    \
    {                                                                                   \
        bvr = *(const float4*)&Bb[(size_t)((k0) + l_row) * Ndim + n0 + l_col];          \
        avr = *(const float4*)&A[(size_t)(m0 + l_am) * Kdim + (k0) + l_ak];             \
    }
#define STS_TILE(buf)                                                                   \
    {                                                                                   \
        uint4 bu; bu.x = f2tf(bvr.x); bu.y = f2tf(bvr.y); bu.z = f2tf(bvr.z); bu.w = f2tf(bvr.w); \
        *(uint4*)&Bs[buf][l_row * SA + l_col] = bu;                                     \
        As[buf][(l_ak + 0) * SA + l_am] = f2tf(avr.x);                                  \
        As[buf][(l_ak + 1) * SA + l_am] = f2tf(avr.y);                                  \
        As[buf][(l_ak + 2) * SA + l_am] = f2tf(avr.z);                                  \
        As[buf][(l_ak + 3) * SA + l_am] = f2tf(avr.w);                                  \
    }

    LDG_TILE(0);
    STS_TILE(0);
    __syncthreads();

    for (int kb = 0; kb < nk; ++kb) {
        const int cur = kb & 1;
        const bool more = (kb + 1 < nk);
        if (more) LDG_TILE((kb + 1) * 16);

#pragma unroll
        for (int k8 = 0; k8 < 16; k8 += 8) {
            uint32_t af[2][4], bf[4][2];
#pragma unroll
            for (int mt = 0; mt < 2; ++mt) {
                int mb = wm * 32 + mt * 16 + r;
                af[mt][0] = As[cur][(k8 + c) * SA + mb];
                af[mt][1] = As[cur][(k8 + c) * SA + mb + 8];
                af[mt][2] = As[cur][(k8 + c + 4) * SA + mb];
                af[mt][3] = As[cur][(k8 + c + 4) * SA + mb + 8];
            }
#pragma unroll
            for (int nt = 0; nt < 4; ++nt) {
                int nb = wn * 32 + nt * 8 + r;
                bf[nt][0] = Bs[cur][(k8 + c) * SA + nb];
                bf[nt][1] = Bs[cur][(k8 + c + 4) * SA + nb];
            }
#pragma unroll
            for (int mt = 0; mt < 2; ++mt)
#pragma unroll
                for (int nt = 0; nt < 4; ++nt)
                    mma_tf32(acc[mt][nt], af[mt], bf[nt]);
        }
        if (more) STS_TILE(cur ^ 1);
        __syncthreads();
    }
#undef LDG_TILE
#undef STS_TILE

#pragma unroll
    for (int mt = 0; mt < 2; ++mt) {
#pragma unroll
        for (int h = 0; h < 2; ++h) {
            const int row = m0 + wm * 32 + mt * 16 + r + h * 8;
            float bval = bias[row];
#pragma unroll
            for (int nt = 0; nt < 4; ++nt) {
                const int col = n0 + wn * 32 + nt * 8 + c * 2;
                float2 o;
                o.x = acc[mt][nt][h * 2 + 0] + bval;
                o.y = acc[mt][nt][h * 2 + 1] + bval;
                *(float2*)&Yb[(size_t)row * Ndim + col] = o;
            }
        }
    }
}

// Fused k+v: grid.z = 32; z<16 -> (wk,bk,g_k), else (wv,bv,g_v). Same pipeline.
__global__ __launch_bounds__(512)
void mma_gemm128_kv(const float* __restrict__ Wk, const float* __restrict__ Wv,
                    const float* __restrict__ B,
                    const float* __restrict__ bk, const float* __restrict__ bv,
                    float* __restrict__ Yk, float* __restrict__ Yv)
{
    __shared__ uint32_t As[2][16 * SA];
    __shared__ uint32_t Bs[2][16 * SA];

    const int tid = threadIdx.x;
    const int zz  = blockIdx.z;
    const int bz  = zz & 15;
    const int sel = zz >> 4;
    const float* A    = sel ? Wv : Wk;
    const float* bias = sel ? bv : bk;
    float*       Y    = sel ? Yv : Yk;
    const float* Bb = B + (size_t)bz * CH * TSL;
    float*       Yb = Y + (size_t)bz * CH * TSL;
    const int m0 = blockIdx.y * 128, n0 = blockIdx.x * 128;

    const int wid = tid >> 5, lane = tid & 31;
    const int wm = wid >> 2, wn = wid & 3;
    const int r = lane >> 2, c = lane & 3;

    const int l_row  = tid >> 5;
    const int l_col  = lane * 4;
    const int l_am   = tid >> 2;
    const int l_ak   = (tid & 3) * 4;

    float acc[2][4][4] = {};
    const int nk = CH / 16;

    float4 avr, bvr;
#define LDG_TILE_KV(k0)                                                                 \
    {                                                                                   \
        bvr = *(const float4*)&Bb[(size_t)((k0) + l_row) * TSL + n0 + l_col];           \
        avr = *(const float4*)&A[(size_t)(m0 + l_am) * CH + (k0) + l_ak];               \
    }
#define STS_TILE_KV(buf)                                                                \
    {                                                                                   \
        uint4 bu; bu.x = f2tf(bvr.x); bu.y = f2tf(bvr.y); bu.z = f2tf(bvr.z); bu.w = f2tf(bvr.w); \
        *(uint4*)&Bs[buf][l_row * SA + l_col] = bu;                                     \
        As[buf][(l_ak + 0) * SA + l_am] = f2tf(avr.x);                                  \
        As[buf][(l_ak + 1) * SA + l_am] = f2tf(avr.y);                                  \
        As[buf][(l_ak + 2) * SA + l_am] = f2tf(avr.z);                                  \
        As[buf][(l_ak + 3) * SA + l_am] = f2tf(avr.w);                                  \
    }

    LDG_TILE_KV(0);
    STS_TILE_KV(0);
    __syncthreads();

    for (int kb = 0; kb < nk; ++kb) {
        const int cur = kb & 1;
        const bool more = (kb + 1 < nk);
        if (more) LDG_TILE_KV((kb + 1) * 16);

#pragma unroll
        for (int k8 = 0; k8 < 16; k8 += 8) {
            uint32_t af[2][4], bf[4][2];
#pragma unroll
            for (int mt = 0; mt < 2; ++mt) {
                int mb = wm * 32 + mt * 16 + r;
                af[mt][0] = As[cur][(k8 + c) * SA + mb];
                af[mt][1] = As[cur][(k8 + c) * SA + mb + 8];
                af[mt][2] = As[cur][(k8 + c + 4) * SA + mb];
                af[mt][3] = As[cur][(k8 + c + 4) * SA + mb + 8];
            }
#pragma unroll
            for (int nt = 0; nt < 4; ++nt) {
                int nb = wn * 32 + nt * 8 + r;
                bf[nt][0] = Bs[cur][(k8 + c) * SA + nb];
                bf[nt][1] = Bs[cur][(k8 + c + 4) * SA + nb];
            }
#pragma unroll
            for (int mt = 0; mt < 2; ++mt)
#pragma unroll
                for (int nt = 0; nt < 4; ++nt)
                    mma_tf32(acc[mt][nt], af[mt], bf[nt]);
        }
        if (more) STS_TILE_KV(cur ^ 1);
        __syncthreads();
    }
#undef LDG_TILE_KV
#undef STS_TILE_KV

#pragma unroll
    for (int mt = 0; mt < 2; ++mt) {
#pragma unroll
        for (int h = 0; h < 2; ++h) {
            const int row = m0 + wm * 32 + mt * 16 + r + h * 8;
            float bval = bias[row];
#pragma unroll
            for (int nt = 0; nt < 4; ++nt) {
                const int col = n0 + wn * 32 + nt * 8 + c * 2;
                float2 o;
                o.x = acc[mt][nt][h * 2 + 0] + bval;
                o.y = acc[mt][nt][h * 2 + 1] + bval;
                *(float2*)&Yb[(size_t)row * TSL + col] = o;
            }
        }
    }
}

// ============================================================================
// Fused flash attention v2 (unchanged from R4 — already split-pipelined)
// ============================================================================
#define FSA 136
#define FSK 72
#define FSV 68
#define FLASH_SMEM ((64*FSA + 64*FSK + 64*FSV + 64*FSA + 512) * 4)

__global__ __launch_bounds__(256, 2)
void flash_attn(const float* __restrict__ Qg, const float* __restrict__ Kg,
                const float* __restrict__ Vg, const float* __restrict__ cmask,
                float* __restrict__ O)
{
    extern __shared__ uint32_t sm[];
    uint32_t* Qs  = sm;                    // [64][136]
    uint32_t* Ks  = sm + 64 * FSA;         // [64][72]   [d][n]
    uint32_t* Vs  = Ks + 64 * FSK;         // [64][68]   [ch][pos]
    uint32_t* Ps  = Vs + 64 * FSV;         // [64][136]  [k][m] / f32 [n][m] epilogue
    float*    cmb = (float*)(Ps + 64 * FSA);  // [512] additive bias

    const int bh = blockIdx.z;
    const int b  = bh >> 2;
    const int m0 = blockIdx.y * 128;
    const int tid = threadIdx.x, wid = tid >> 5, lane = tid & 31;
    const int r = lane >> 2, c = lane & 3;
    const int mb = wid * 16 + r;

    const float* Qb = Qg + (size_t)bh * KC * TT;
    const float* Kb = Kg + (size_t)bh * KC * TSL;
    const float* Vb = Vg + (size_t)bh * KC * TSL;

    // ---- load Q tile (64 x 128) with RoPE ----
    {
        int d  = tid >> 3;          // 0..31
        int mg = (tid & 7) * 16;
#pragma unroll
        for (int j = 0; j < 16; j += 4) {
            int m = mg + j;
            int t = m0 + m;
            float4 q1 = *(const float4*)&Qb[(size_t)d * TT + t];
            float4 q2 = *(const float4*)&Qb[(size_t)(d + 32) * TT + t];
            float4 cv = *(const float4*)&g_cos[(size_t)d * TT + t];
            float4 sv = *(const float4*)&g_sin[(size_t)d * TT + t];
            Qs[d * FSA + m + 0] = f2tf(q1.x * cv.x - q2.x * sv.x);
            Qs[d * FSA + m + 1] = f2tf(q1.y * cv.y - q2.y * sv.y);
            Qs[d * FSA + m + 2] = f2tf(q1.z * cv.z - q2.z * sv.z);
            Qs[d * FSA + m + 3] = f2tf(q1.w * cv.w - q2.w * sv.w);
            Qs[(d + 32) * FSA + m + 0] = f2tf(q2.x * cv.x + q1.x * sv.x);
            Qs[(d + 32) * FSA + m + 1] = f2tf(q2.y * cv.y + q1.y * sv.y);
            Qs[(d + 32) * FSA + m + 2] = f2tf(q2.z * cv.z + q1.z * sv.z);
            Qs[(d + 32) * FSA + m + 3] = f2tf(q2.w * cv.w + q1.w * sv.w);
        }
    }
    // ---- cmask -> additive bias in smem ----
    for (int i = tid; i < TSL; i += 256)
        cmb[i] = (cmask[(size_t)b * TSL + i] == 0.f) ? -1e4f : 0.f;

    // ---- prefetch chunk 0 into registers ----
    const int prow = tid >> 2;          // 0..63
    const int pcol = (tid & 3) * 4;     // col = pcol + 16*j
    float4 kr[4], vr[4];
#pragma unroll
    for (int j = 0; j < 4; ++j) {
        kr[j] = *(const float4*)&Kb[(size_t)prow * TSL + pcol + 16 * j];
        vr[j] = *(const float4*)&Vb[(size_t)prow * TSL + pcol + 16 * j];
    }

    float m_run[2] = {-1e30f, -1e30f};
    float l_run[2] = {0.f, 0.f};
    float acc_o[8][4] = {};

    __syncthreads();   // Qs + cmb visible

    for (int ci = 0; ci < 8; ++ci) {
        const int s0 = ci * 64;
        // ---- store prefetched K/V into smem (tf32) ----
#pragma unroll
        for (int j = 0; j < 4; ++j) {
            int col = pcol + 16 * j;
            Ks[prow * FSK + col + 0] = f2tf(kr[j].x);
            Ks[prow * FSK + col + 1] = f2tf(kr[j].y);
            Ks[prow * FSK + col + 2] = f2tf(kr[j].z);
            Ks[prow * FSK + col + 3] = f2tf(kr[j].w);
            Vs[prow * FSV + col + 0] = f2tf(vr[j].x);
            Vs[prow * FSV + col + 1] = f2tf(vr[j].y);
            Vs[prow * FSV + col + 2] = f2tf(vr[j].z);
            Vs[prow * FSV + col + 3] = f2tf(vr[j].w);
        }
        __syncthreads();
        // ---- prefetch next chunk ----
        if (ci < 7) {
#pragma unroll
            for (int j = 0; j < 4; ++j) {
                kr[j] = *(const float4*)&Kb[(size_t)prow * TSL + s0 + 64 + pcol + 16 * j];
                vr[j] = *(const float4*)&Vb[(size_t)prow * TSL + s0 + 64 + pcol + 16 * j];
            }
        }

        // ---- S = Q^T K : warp tile 16 x 64 ----
        float acc_s[8][4] = {};
#pragma unroll
        for (int k8 = 0; k8 < 64; k8 += 8) {
            uint32_t af[4];
            af[0] = Qs[(k8 + c) * FSA + mb];
            af[1] = Qs[(k8 + c) * FSA + mb + 8];
            af[2] = Qs[(k8 + c + 4) * FSA + mb];
            af[3] = Qs[(k8 + c + 4) * FSA + mb + 8];
#pragma unroll
            for (int nt = 0; nt < 8; ++nt) {
                uint32_t bf[2];
                bf[0] = Ks[(k8 + c) * FSK + nt * 8 + r];
                bf[1] = Ks[(k8 + c + 4) * FSK + nt * 8 + r];
                mma_tf32(acc_s[nt], af, bf);
            }
        }

        // ---- scale + bias + online softmax (warp-local rows) ----
        float mx[2] = {-1e30f, -1e30f};
#pragma unroll
        for (int nt = 0; nt < 8; ++nt) {
            float2 bias = *(float2*)&cmb[s0 + nt * 8 + 2 * c];
#pragma unroll
            for (int jj = 0; jj < 4; ++jj) {
                float v = acc_s[nt][jj] * 0.125f + ((jj & 1) ? bias.y : bias.x);
                acc_s[nt][jj] = v;
                mx[jj >> 1] = fmaxf(mx[jj >> 1], v);
            }
        }
#pragma unroll
        for (int h = 0; h < 2; ++h) {
            mx[h] = fmaxf(mx[h], __shfl_xor_sync(0xffffffffu, mx[h], 1));
            mx[h] = fmaxf(mx[h], __shfl_xor_sync(0xffffffffu, mx[h], 2));
        }
        float mnew[2], scale[2], lad[2] = {0.f, 0.f};
#pragma unroll
        for (int h = 0; h < 2; ++h) {
            mnew[h]  = fmaxf(m_run[h], mx[h]);
            scale[h] = __expf(m_run[h] - mnew[h]);
            m_run[h] = mnew[h];
        }
#pragma unroll
        for (int nt = 0; nt < 8; ++nt) {
#pragma unroll
            for (int jj = 0; jj < 4; ++jj) {
                float e = __expf(acc_s[nt][jj] - mnew[jj >> 1]);
                acc_s[nt][jj] = e;
                lad[jj >> 1] += e;
            }
        }
#pragma unroll
        for (int h = 0; h < 2; ++h) {
            lad[h] += __shfl_xor_sync(0xffffffffu, lad[h], 1);
            lad[h] += __shfl_xor_sync(0xffffffffu, lad[h], 2);
            l_run[h] = l_run[h] * scale[h] + lad[h];
        }
#pragma unroll
        for (int nt = 0; nt < 8; ++nt) {
#pragma unroll
            for (int jj = 0; jj < 4; ++jj)
                acc_o[nt][jj] *= scale[jj >> 1];
        }
        // P -> smem [k][m] (warp-private m-stripe)
#pragma unroll
        for (int nt = 0; nt < 8; ++nt) {
#pragma unroll
            for (int jj = 0; jj < 4; ++jj) {
                int kcol = nt * 8 + 2 * c + (jj & 1);
                int mrow = wid * 16 + r + (jj >> 1) * 8;
                Ps[kcol * FSA + mrow] = f2tf(acc_s[nt][jj]);
            }
        }
        __syncwarp();

        // ---- O += P @ V^T ----
#pragma unroll
        for (int k8 = 0; k8 < 64; k8 += 8) {
            uint32_t af[4];
            af[0] = Ps[(k8 + c) * FSA + mb];
            af[1] = Ps[(k8 + c) * FSA + mb + 8];
            af[2] = Ps[(k8 + c + 4) * FSA + mb];
            af[3] = Ps[(k8 + c + 4) * FSA + mb + 8];
#pragma unroll
            for (int nt = 0; nt < 8; ++nt) {
                uint32_t bf[2];
                bf[0] = Vs[(nt * 8 + r) * FSV + k8 + c];
                bf[1] = Vs[(nt * 8 + r) * FSV + k8 + c + 4];
                mma_tf32(acc_o[nt], af, bf);
            }
        }
        __syncthreads();   // smem reads done before next chunk's stores
    }

    // ---- epilogue: /l, transpose via smem, coalesced store ----
    float inv[2] = {1.f / l_run[0], 1.f / l_run[1]};
    float* Pf = (float*)Ps;
#pragma unroll
    for (int nt = 0; nt < 8; ++nt) {
#pragma unroll
        for (int jj = 0; jj < 4; ++jj) {
            int n = nt * 8 + 2 * c + (jj & 1);
            int m = wid * 16 + r + (jj >> 1) * 8;
            Pf[n * FSA + m] = acc_o[nt][jj] * inv[jj >> 1];
        }
    }
    __syncthreads();
    {
        int row = tid >> 2;          // 0..63 (output channel)
        int mq  = (tid & 3) * 4;
#pragma unroll
        for (int j = 0; j < 8; ++j) {
            int m = mq + 16 * j;
            *(float4*)&O[((size_t)bh * KC + row) * TT + m0 + m] =
                *(float4*)&Pf[row * FSA + m];
        }
    }
}

// ============================================================================
// Fused FiLM GEMM — split LDG/compute/STS pipeline.
// ============================================================================
#define FILM_SMEM ((3 * 2 * 16 * SA) * 4)

__global__ __launch_bounds__(512)
void film_gemm(const float* __restrict__ Wf, const float* __restrict__ Yin,
               const float* __restrict__ bfilm, const float* __restrict__ x,
               const float* __restrict__ xmask, float* __restrict__ out)
{
    extern __shared__ uint32_t smf[];
    uint32_t* AsG = smf;
    uint32_t* AsB = smf + 2 * 16 * SA;
    uint32_t* Bs  = smf + 4 * 16 * SA;

    const int tid = threadIdx.x;
    const int bz  = blockIdx.z;
    const float* Bb = Yin + (size_t)bz * CH * TT;
    const int m0 = blockIdx.y * 128, n0 = blockIdx.x * 128;

    const int wid = tid >> 5, lane = tid & 31;
    const int wm = wid >> 2, wn = wid & 3;
    const int r = lane >> 2, c = lane & 3;

    const int l_row = tid >> 5;
    const int l_col = lane * 4;
    const int l_am  = tid >> 2;
    const int l_ak  = (tid & 3) * 4;

    float acc_g[2][4][4] = {};
    float acc_b[2][4][4] = {};

    float4 bvr, agr, abr;
#define LDG_TILE_F(k0)                                                                  \
    {                                                                                   \
        bvr = *(const float4*)&Bb[(size_t)((k0) + l_row) * TT + n0 + l_col];            \
        agr = *(const float4*)&Wf[(size_t)(m0 + l_am) * CH + (k0) + l_ak];              \
        abr = *(const float4*)&Wf[(size_t)(256 + m0 + l_am) * CH + (k0) + l_ak];        \
    }
#define STS_TILE_F(buf)                                                                 \
    {                                                                                   \
        uint4 bu; bu.x = f2tf(bvr.x); bu.y = f2tf(bvr.y); bu.z = f2tf(bvr.z); bu.w = f2tf(bvr.w); \
        *(uint4*)&Bs[(buf) * 16 * SA + l_row * SA + l_col] = bu;                        \
        AsG[(buf) * 16 * SA + (l_ak + 0) * SA + l_am] = f2tf(agr.x);                    \
        AsG[(buf) * 16 * SA + (l_ak + 1) * SA + l_am] = f2tf(agr.y);                    \
        AsG[(buf) * 16 * SA + (l_ak + 2) * SA + l_am] = f2tf(agr.z);                    \
        AsG[(buf) * 16 * SA + (l_ak + 3) * SA + l_am] = f2tf(agr.w);                    \
        AsB[(buf) * 16 * SA + (l_ak + 0) * SA + l_am] = f2tf(abr.x);                    \
        AsB[(buf) * 16 * SA + (l_ak + 1) * SA + l_am] = f2tf(abr.y);                    \
        AsB[(buf) * 16 * SA + (l_ak + 2) * SA + l_am] = f2tf(abr.z);                    \
        AsB[(buf) * 16 * SA + (l_ak + 3) * SA + l_am] = f2tf(abr.w);                    \
    }

    LDG_TILE_F(0);
    STS_TILE_F(0);
    __syncthreads();

    const int nk = CH / 16;
    for (int kb = 0; kb < nk; ++kb) {
        const int cur = kb & 1;
        const bool more = (kb + 1 < nk);
        if (more) LDG_TILE_F((kb + 1) * 16);

#pragma unroll
        for (int k8 = 0; k8 < 16; k8 += 8) {
            uint32_t afg[2][4], afb[2][4], bf[4][2];
#pragma unroll
            for (int mt = 0; mt < 2; ++mt) {
                int mbx = wm * 32 + mt * 16 + r;
                afg[mt][0] = AsG[cur * 16 * SA + (k8 + c) * SA + mbx];
                afg[mt][1] = AsG[cur * 16 * SA + (k8 + c) * SA + mbx + 8];
                afg[mt][2] = AsG[cur * 16 * SA + (k8 + c + 4) * SA + mbx];
                afg[mt][3] = AsG[cur * 16 * SA + (k8 + c + 4) * SA + mbx + 8];
                afb[mt][0] = AsB[cur * 16 * SA + (k8 + c) * SA + mbx];
                afb[mt][1] = AsB[cur * 16 * SA + (k8 + c) * SA + mbx + 8];
                afb[mt][2] = AsB[cur * 16 * SA + (k8 + c + 4) * SA + mbx];
                afb[mt][3] = AsB[cur * 16 * SA + (k8 + c + 4) * SA + mbx + 8];
            }
#pragma unroll
            for (int nt = 0; nt < 4; ++nt) {
                int nb = wn * 32 + nt * 8 + r;
                bf[nt][0] = Bs[cur * 16 * SA + (k8 + c) * SA + nb];
                bf[nt][1] = Bs[cur * 16 * SA + (k8 + c + 4) * SA + nb];
            }
#pragma unroll
            for (int mt = 0; mt < 2; ++mt)
#pragma unroll
                for (int nt = 0; nt < 4; ++nt) {
                    mma_tf32(acc_g[mt][nt], afg[mt], bf[nt]);
                    mma_tf32(acc_b[mt][nt], afb[mt], bf[nt]);
                }
        }
        if (more) STS_TILE_F(cur ^ 1);
        __syncthreads();
    }
#undef LDG_TILE_F
#undef STS_TILE_F

#pragma unroll
    for (int mt = 0; mt < 2; ++mt) {
#pragma unroll
        for (int h = 0; h < 2; ++h) {
            const int row = m0 + wm * 32 + mt * 16 + r + h * 8;
            float bg = bfilm[row];
            float bb = bfilm[256 + row];
#pragma unroll
            for (int nt = 0; nt < 4; ++nt) {
                const int col = n0 + wn * 32 + nt * 8 + c * 2;
                float g0  = acc_g[mt][nt][h * 2 + 0] + bg;
                float g1  = acc_g[mt][nt][h * 2 + 1] + bg;
                float be0 = acc_b[mt][nt][h * 2 + 0] + bb;
                float be1 = acc_b[mt][nt][h * 2 + 1] + bb;
                float2 xv = *(const float2*)&x[((size_t)bz * CH + row) * TT + col];
                float xmm0 = xmask[(size_t)bz * TT + col];
                float xmm1 = xmask[(size_t)bz * TT + col + 1];
                float2 o;
                o.x = (xv.x * g0 + be0) * xmm0;
                o.y = (xv.y * g1 + be1) * xmm1;
                *(float2*)&out[((size_t)bz * CH + row) * TT + col] = o;
            }
        }
    }
}

// ---------------- launch ----------------
extern "C" void kernel_launch(void* const* d_in, const int* in_sizes, int n_in,
                              void* d_out, int out_size) {
    const float* x           = (const float*)d_in[0];
    const float* x_mask      = (const float*)d_in[1];
    const float* cond_latent = (const float*)d_in[2];
    const float* cond_mask   = (const float*)d_in[3];
    const float* w_cond      = (const float*)d_in[4];
    const float* b_cond      = (const float*)d_in[5];
    const float* wq          = (const float*)d_in[6];
    const float* bq          = (const float*)d_in[7];
    const float* wk          = (const float*)d_in[8];
    const float* bk          = (const float*)d_in[9];
    const float* wv          = (const float*)d_in[10];
    const float* bv          = (const float*)d_in[11];
    const float* wo          = (const float*)d_in[12];
    const float* bo          = (const float*)d_in[13];
    const float* w_film      = (const float*)d_in[14];
    const float* b_film      = (const float*)d_in[15];
    float* out = (float*)d_out;

    float *p_c, *p_q, *p_k, *p_v, *p_att, *p_y;
    cudaGetSymbolAddress((void**)&p_c,   g_c);
    cudaGetSymbolAddress((void**)&p_q,   g_q);
    cudaGetSymbolAddress((void**)&p_k,   g_k);
    cudaGetSymbolAddress((void**)&p_v,   g_v);
    cudaGetSymbolAddress((void**)&p_att, g_att);
    cudaGetSymbolAddress((void**)&p_y,   g_y);

    cudaFuncSetAttribute(flash_attn, cudaFuncAttributeMaxDynamicSharedMemorySize, FLASH_SMEM);
    cudaFuncSetAttribute(film_gemm,  cudaFuncAttributeMaxDynamicSharedMemorySize, FILM_SMEM);

    // RoPE tables [d][t]
    rope_table_kernel<<<(32 * TT + 255) / 256, 256>>>();

    // c = w_cond @ cond_latent + b_cond     [b][256][512]
    mma_gemm128<<<dim3(TSL / 128, CH / 128, BQ), 512>>>(
        w_cond, cond_latent, b_cond, p_c,
        TSL, CONDC, (size_t)CONDC * TSL, (size_t)CH * TSL);

    // q = wq @ x + bq                        [b][256][2048]
    mma_gemm128<<<dim3(TT / 128, CH / 128, BQ), 512>>>(
        wq, x, bq, p_q,
        TT, CH, (size_t)CH * TT, (size_t)CH * TT);

    // k and v fused in one launch (fills the chip)
    mma_gemm128_kv<<<dim3(TSL / 128, CH / 128, 2 * BQ), 512>>>(
        wk, wv, p_c, bk, bv, p_k, p_v);

    // pre-rope + cond-mask K in place
    rope_k_mask_kernel<<<(BQ * NH * 32 * TSL + 255) / 256, 256>>>(p_k, cond_mask);

    // fused attention (Q-rope + scores + bias-mask + softmax + P@V)
    flash_attn<<<dim3(1, TT / 128, BQ * NH), 256, FLASH_SMEM>>>(
        p_q, p_k, p_v, cond_mask, p_att);

    // y = wo @ att + bo
    mma_gemm128<<<dim3(TT / 128, CH / 128, BQ), 512>>>(
        wo, p_att, bo, p_y,
        TT, CH, (size_t)CH * TT, (size_t)CH * TT);

    // fused FiLM
    film_gemm<<<dim3(TT / 128, CH / 128, BQ), 512, FILM_SMEM>>>(
        w_film, p_y, b_film, x, x_mask, out);
}

// round 6
// speedup vs baseline: 2.8938x; 1.0522x over previous
#include <cuda_runtime.h>
#include <math.h>
#include <stdint.h>

// ---------------- problem constants (fixed shapes) ----------------
#define BQ   16      // batch
#define CH   256     // hidden
#define CONDC 512    // cond channels
#define TT   2048    // target length
#define TSL  512     // source length
#define NH   4       // heads
#define KC   64      // head dim

#define SA 136       // padded smem stride (words): mod 32 = 8 (CF fragment loads), *4 % 16 == 0

// ---------------- scratch (device globals; no allocation) ----------------
__device__ float g_c  [BQ * CH * TSL];        // cond proj           [b][C][Ts]
__device__ float g_q  [BQ * CH * TT];         // q (un-roped)        [bh][64][Tt]
__device__ float g_k  [BQ * CH * TSL];        // k (roped+masked)    [bh][64][Ts]
__device__ float g_v  [BQ * CH * TSL];        // v                   [bh][64][Ts]
__device__ float g_att[BQ * CH * TT];         // attn out            [b][C][Tt]
__device__ float g_y  [BQ * CH * TT];         // wo proj             [b][C][Tt]
__device__ float g_cos[32 * TT];              // [d][t]
__device__ float g_sin[32 * TT];

// ---------------- tf32 helpers ----------------
__device__ __forceinline__ uint32_t f2tf(float f) {
    uint32_t u;
    asm("cvt.rna.tf32.f32 %0, %1;" : "=r"(u) : "f"(f));
    return u;
}

__device__ __forceinline__ void mma_tf32(float* c, const uint32_t* a, const uint32_t* b) {
    asm volatile(
        "mma.sync.aligned.m16n8k8.row.col.f32.tf32.tf32.f32 "
        "{%0,%1,%2,%3}, {%4,%5,%6,%7}, {%8,%9}, {%0,%1,%2,%3};\n"
        : "+f"(c[0]), "+f"(c[1]), "+f"(c[2]), "+f"(c[3])
        : "r"(a[0]), "r"(a[1]), "r"(a[2]), "r"(a[3]), "r"(b[0]), "r"(b[1]));
}

// ---------------- RoPE tables, layout [d][t] ----------------
__global__ void rope_table_kernel() {
    int idx = blockIdx.x * blockDim.x + threadIdx.x;
    if (idx >= 32 * TT) return;
    int d = idx / TT;
    int t = idx % TT;
    float invf = (float)pow(10000.0, -(double)d / 32.0);
    float ang  = (float)t * invf;            // same fp32 rounding as reference
    g_cos[idx] = (float)cos((double)ang);
    g_sin[idx] = (float)sin((double)ang);
}

// ---------------- pre-rope + mask K in place: [bh][64][Ts] ----------------
__global__ void rope_k_mask_kernel(float* __restrict__ k, const float* __restrict__ cmask) {
    int idx = blockIdx.x * blockDim.x + threadIdx.x;
    if (idx >= BQ * NH * 32 * TSL) return;
    int t  = idx & (TSL - 1);
    int rr = idx >> 9;            // TSL = 512
    int d  = rr & 31;
    int bh = rr >> 5;
    int b  = bh >> 2;
    float cs = g_cos[d * TT + t];
    float sn = g_sin[d * TT + t];
    float cm = cmask[(size_t)b * TSL + t];
    size_t base = ((size_t)bh * KC + d) * TSL + t;
    float k1 = k[base];
    float k2 = k[base + (size_t)32 * TSL];
    k[base]                    = (k1 * cs - k2 * sn) * cm;
    k[base + (size_t)32 * TSL] = (k2 * cs + k1 * sn) * cm;
}

// ============================================================================
// tf32 MMA GEMM, 128x128 CTA tile, 256 threads (8 warps, 2x4 grid),
// warp tile 64x32 -> 1.5 LDS words per MMA. BK=16, double-buffered.
// A stored [M][K] global -> transpose-on-load. Y = A@B + bias[m].
// GSEL: 0 = plain (A,bias,Y args used directly);
//       1 = kv-fused (blockIdx.z>>4 selects wk/wv set).
// ============================================================================
template<int GSEL>
__global__ __launch_bounds__(256, 2)
void mma_gemm64(const float* __restrict__ A0, const float* __restrict__ A1,
                const float* __restrict__ B,
                const float* __restrict__ bias0, const float* __restrict__ bias1,
                float* __restrict__ Y0, float* __restrict__ Y1,
                int Ndim, int Kdim, size_t strideB, size_t strideY)
{
    __shared__ uint32_t As[2][16 * SA];
    __shared__ uint32_t Bs[2][16 * SA];

    const int tid = threadIdx.x;
    int bz, sel = 0;
    if (GSEL == 1) { bz = blockIdx.z & 15; sel = blockIdx.z >> 4; }
    else           { bz = blockIdx.z; }
    const float* A    = (GSEL == 1 && sel) ? A1 : A0;
    const float* bias = (GSEL == 1 && sel) ? bias1 : bias0;
    float*       Y    = (GSEL == 1 && sel) ? Y1 : Y0;
    const float* Bb = B + (size_t)bz * strideB;
    float*       Yb = Y + (size_t)bz * strideY;
    const int m0 = blockIdx.y * 128, n0 = blockIdx.x * 128;

    const int wid = tid >> 5, lane = tid & 31;
    const int wm = wid >> 2, wn = wid & 3;       // 2x4 warp grid, 64x32 warp tile
    const int r = lane >> 2, c = lane & 3;

    // loaders: A 128x16 (8 words/thread), B 16x128 (8 words/thread)
    const int l_am  = tid >> 1;           // 0..127
    const int l_ak  = (tid & 1) * 8;      // 0 or 8
    const int l_row = tid >> 4;           // 0..15
    const int l_col = (tid & 15) * 8;     // 0..120

    float acc[4][4][4] = {};
    const int nk = Kdim / 16;

    float4 avr0, avr1, bvr0, bvr1;
#define LDG_T(k0)                                                                       \
    {                                                                                   \
        avr0 = *(const float4*)&A[(size_t)(m0 + l_am) * Kdim + (k0) + l_ak];            \
        avr1 = *(const float4*)&A[(size_t)(m0 + l_am) * Kdim + (k0) + l_ak + 4];        \
        bvr0 = *(const float4*)&Bb[(size_t)((k0) + l_row) * Ndim + n0 + l_col];         \
        bvr1 = *(const float4*)&Bb[(size_t)((k0) + l_row) * Ndim + n0 + l_col + 4];     \
    }
#define STS_T(buf)                                                                      \
    {                                                                                   \
        As[buf][(l_ak + 0) * SA + l_am] = f2tf(avr0.x);                                 \
        As[buf][(l_ak + 1) * SA + l_am] = f2tf(avr0.y);                                 \
        As[buf][(l_ak + 2) * SA + l_am] = f2tf(avr0.z);                                 \
        As[buf][(l_ak + 3) * SA + l_am] = f2tf(avr0.w);                                 \
        As[buf][(l_ak + 4) * SA + l_am] = f2tf(avr1.x);                                 \
        As[buf][(l_ak + 5) * SA + l_am] = f2tf(avr1.y);                                 \
        As[buf][(l_ak + 6) * SA + l_am] = f2tf(avr1.z);                                 \
        As[buf][(l_ak + 7) * SA + l_am] = f2tf(avr1.w);                                 \
        uint4 bu0; bu0.x = f2tf(bvr0.x); bu0.y = f2tf(bvr0.y); bu0.z = f2tf(bvr0.z); bu0.w = f2tf(bvr0.w); \
        uint4 bu1; bu1.x = f2tf(bvr1.x); bu1.y = f2tf(bvr1.y); bu1.z = f2tf(bvr1.z); bu1.w = f2tf(bvr1.w); \
        *(uint4*)&Bs[buf][l_row * SA + l_col]     = bu0;                                \
        *(uint4*)&Bs[buf][l_row * SA + l_col + 4] = bu1;                                \
    }

    LDG_T(0);
    STS_T(0);
    __syncthreads();

    for (int kb = 0; kb < nk; ++kb) {
        const int cur = kb & 1;
        const bool more = (kb + 1 < nk);
        if (more) LDG_T((kb + 1) * 16);

#pragma unroll
        for (int k8 = 0; k8 < 16; k8 += 8) {
            uint32_t af[4][4], bf[4][2];
#pragma unroll
            for (int mt = 0; mt < 4; ++mt) {
                int mb = wm * 64 + mt * 16 + r;
                af[mt][0] = As[cur][(k8 + c) * SA + mb];
                af[mt][1] = As[cur][(k8 + c) * SA + mb + 8];
                af[mt][2] = As[cur][(k8 + c + 4) * SA + mb];
                af[mt][3] = As[cur][(k8 + c + 4) * SA + mb + 8];
            }
#pragma unroll
            for (int nt = 0; nt < 4; ++nt) {
                int nb = wn * 32 + nt * 8 + r;
                bf[nt][0] = Bs[cur][(k8 + c) * SA + nb];
                bf[nt][1] = Bs[cur][(k8 + c + 4) * SA + nb];
            }
#pragma unroll
            for (int mt = 0; mt < 4; ++mt)
#pragma unroll
                for (int nt = 0; nt < 4; ++nt)
                    mma_tf32(acc[mt][nt], af[mt], bf[nt]);
        }
        if (more) STS_T(cur ^ 1);
        __syncthreads();
    }
#undef LDG_T
#undef STS_T

#pragma unroll
    for (int mt = 0; mt < 4; ++mt) {
#pragma unroll
        for (int h = 0; h < 2; ++h) {
            const int row = m0 + wm * 64 + mt * 16 + h * 8 + r;
            float bval = bias[row];
#pragma unroll
            for (int nt = 0; nt < 4; ++nt) {
                const int col = n0 + wn * 32 + nt * 8 + c * 2;
                float2 o;
                o.x = acc[mt][nt][h * 2 + 0] + bval;
                o.y = acc[mt][nt][h * 2 + 1] + bval;
                *(float2*)&Yb[(size_t)row * Ndim + col] = o;
            }
        }
    }
}

// ============================================================================
// Fused flash attention (unchanged from R5)
// ============================================================================
#define FSA 136
#define FSK 72
#define FSV 68
#define FLASH_SMEM ((64*FSA + 64*FSK + 64*FSV + 64*FSA + 512) * 4)

__global__ __launch_bounds__(256, 2)
void flash_attn(const float* __restrict__ Qg, const float* __restrict__ Kg,
                const float* __restrict__ Vg, const float* __restrict__ cmask,
                float* __restrict__ O)
{
    extern __shared__ uint32_t sm[];
    uint32_t* Qs  = sm;                    // [64][136]
    uint32_t* Ks  = sm + 64 * FSA;         // [64][72]   [d][n]
    uint32_t* Vs  = Ks + 64 * FSK;         // [64][68]   [ch][pos]
    uint32_t* Ps  = Vs + 64 * FSV;         // [64][136]  [k][m] / f32 [n][m] epilogue
    float*    cmb = (float*)(Ps + 64 * FSA);  // [512] additive bias

    const int bh = blockIdx.z;
    const int b  = bh >> 2;
    const int m0 = blockIdx.y * 128;
    const int tid = threadIdx.x, wid = tid >> 5, lane = tid & 31;
    const int r = lane >> 2, c = lane & 3;
    const int mb = wid * 16 + r;

    const float* Qb = Qg + (size_t)bh * KC * TT;
    const float* Kb = Kg + (size_t)bh * KC * TSL;
    const float* Vb = Vg + (size_t)bh * KC * TSL;

    // ---- load Q tile (64 x 128) with RoPE ----
    {
        int d  = tid >> 3;          // 0..31
        int mg = (tid & 7) * 16;
#pragma unroll
        for (int j = 0; j < 16; j += 4) {
            int m = mg + j;
            int t = m0 + m;
            float4 q1 = *(const float4*)&Qb[(size_t)d * TT + t];
            float4 q2 = *(const float4*)&Qb[(size_t)(d + 32) * TT + t];
            float4 cv = *(const float4*)&g_cos[(size_t)d * TT + t];
            float4 sv = *(const float4*)&g_sin[(size_t)d * TT + t];
            Qs[d * FSA + m + 0] = f2tf(q1.x * cv.x - q2.x * sv.x);
            Qs[d * FSA + m + 1] = f2tf(q1.y * cv.y - q2.y * sv.y);
            Qs[d * FSA + m + 2] = f2tf(q1.z * cv.z - q2.z * sv.z);
            Qs[d * FSA + m + 3] = f2tf(q1.w * cv.w - q2.w * sv.w);
            Qs[(d + 32) * FSA + m + 0] = f2tf(q2.x * cv.x + q1.x * sv.x);
            Qs[(d + 32) * FSA + m + 1] = f2tf(q2.y * cv.y + q1.y * sv.y);
            Qs[(d + 32) * FSA + m + 2] = f2tf(q2.z * cv.z + q1.z * sv.z);
            Qs[(d + 32) * FSA + m + 3] = f2tf(q2.w * cv.w + q1.w * sv.w);
        }
    }
    // ---- cmask -> additive bias in smem ----
    for (int i = tid; i < TSL; i += 256)
        cmb[i] = (cmask[(size_t)b * TSL + i] == 0.f) ? -1e4f : 0.f;

    // ---- prefetch chunk 0 into registers ----
    const int prow = tid >> 2;          // 0..63
    const int pcol = (tid & 3) * 4;     // col = pcol + 16*j
    float4 kr[4], vr[4];
#pragma unroll
    for (int j = 0; j < 4; ++j) {
        kr[j] = *(const float4*)&Kb[(size_t)prow * TSL + pcol + 16 * j];
        vr[j] = *(const float4*)&Vb[(size_t)prow * TSL + pcol + 16 * j];
    }

    float m_run[2] = {-1e30f, -1e30f};
    float l_run[2] = {0.f, 0.f};
    float acc_o[8][4] = {};

    __syncthreads();   // Qs + cmb visible

    for (int ci = 0; ci < 8; ++ci) {
        const int s0 = ci * 64;
        // ---- store prefetched K/V into smem (tf32) ----
#pragma unroll
        for (int j = 0; j < 4; ++j) {
            int col = pcol + 16 * j;
            Ks[prow * FSK + col + 0] = f2tf(kr[j].x);
            Ks[prow * FSK + col + 1] = f2tf(kr[j].y);
            Ks[prow * FSK + col + 2] = f2tf(kr[j].z);
            Ks[prow * FSK + col + 3] = f2tf(kr[j].w);
            Vs[prow * FSV + col + 0] = f2tf(vr[j].x);
            Vs[prow * FSV + col + 1] = f2tf(vr[j].y);
            Vs[prow * FSV + col + 2] = f2tf(vr[j].z);
            Vs[prow * FSV + col + 3] = f2tf(vr[j].w);
        }
        __syncthreads();
        // ---- prefetch next chunk ----
        if (ci < 7) {
#pragma unroll
            for (int j = 0; j < 4; ++j) {
                kr[j] = *(const float4*)&Kb[(size_t)prow * TSL + s0 + 64 + pcol + 16 * j];
                vr[j] = *(const float4*)&Vb[(size_t)prow * TSL + s0 + 64 + pcol + 16 * j];
            }
        }

        // ---- S = Q^T K : warp tile 16 x 64 ----
        float acc_s[8][4] = {};
#pragma unroll
        for (int k8 = 0; k8 < 64; k8 += 8) {
            uint32_t af[4];
            af[0] = Qs[(k8 + c) * FSA + mb];
            af[1] = Qs[(k8 + c) * FSA + mb + 8];
            af[2] = Qs[(k8 + c + 4) * FSA + mb];
            af[3] = Qs[(k8 + c + 4) * FSA + mb + 8];
#pragma unroll
            for (int nt = 0; nt < 8; ++nt) {
                uint32_t bf[2];
                bf[0] = Ks[(k8 + c) * FSK + nt * 8 + r];
                bf[1] = Ks[(k8 + c + 4) * FSK + nt * 8 + r];
                mma_tf32(acc_s[nt], af, bf);
            }
        }

        // ---- scale + bias + online softmax (warp-local rows) ----
        float mx[2] = {-1e30f, -1e30f};
#pragma unroll
        for (int nt = 0; nt < 8; ++nt) {
            float2 bias = *(float2*)&cmb[s0 + nt * 8 + 2 * c];
#pragma unroll
            for (int jj = 0; jj < 4; ++jj) {
                float v = acc_s[nt][jj] * 0.125f + ((jj & 1) ? bias.y : bias.x);
                acc_s[nt][jj] = v;
                mx[jj >> 1] = fmaxf(mx[jj >> 1], v);
            }
        }
#pragma unroll
        for (int h = 0; h < 2; ++h) {
            mx[h] = fmaxf(mx[h], __shfl_xor_sync(0xffffffffu, mx[h], 1));
            mx[h] = fmaxf(mx[h], __shfl_xor_sync(0xffffffffu, mx[h], 2));
        }
        float mnew[2], scale[2], lad[2] = {0.f, 0.f};
#pragma unroll
        for (int h = 0; h < 2; ++h) {
            mnew[h]  = fmaxf(m_run[h], mx[h]);
            scale[h] = __expf(m_run[h] - mnew[h]);
            m_run[h] = mnew[h];
        }
#pragma unroll
        for (int nt = 0; nt < 8; ++nt) {
#pragma unroll
            for (int jj = 0; jj < 4; ++jj) {
                float e = __expf(acc_s[nt][jj] - mnew[jj >> 1]);
                acc_s[nt][jj] = e;
                lad[jj >> 1] += e;
            }
        }
#pragma unroll
        for (int h = 0; h < 2; ++h) {
            lad[h] += __shfl_xor_sync(0xffffffffu, lad[h], 1);
            lad[h] += __shfl_xor_sync(0xffffffffu, lad[h], 2);
            l_run[h] = l_run[h] * scale[h] + lad[h];
        }
#pragma unroll
        for (int nt = 0; nt < 8; ++nt) {
#pragma unroll
            for (int jj = 0; jj < 4; ++jj)
                acc_o[nt][jj] *= scale[jj >> 1];
        }
        // P -> smem [k][m] (warp-private m-stripe)
#pragma unroll
        for (int nt = 0; nt < 8; ++nt) {
#pragma unroll
            for (int jj = 0; jj < 4; ++jj) {
                int kcol = nt * 8 + 2 * c + (jj & 1);
                int mrow = wid * 16 + r + (jj >> 1) * 8;
                Ps[kcol * FSA + mrow] = f2tf(acc_s[nt][jj]);
            }
        }
        __syncwarp();

        // ---- O += P @ V^T ----
#pragma unroll
        for (int k8 = 0; k8 < 64; k8 += 8) {
            uint32_t af[4];
            af[0] = Ps[(k8 + c) * FSA + mb];
            af[1] = Ps[(k8 + c) * FSA + mb + 8];
            af[2] = Ps[(k8 + c + 4) * FSA + mb];
            af[3] = Ps[(k8 + c + 4) * FSA + mb + 8];
#pragma unroll
            for (int nt = 0; nt < 8; ++nt) {
                uint32_t bf[2];
                bf[0] = Vs[(nt * 8 + r) * FSV + k8 + c];
                bf[1] = Vs[(nt * 8 + r) * FSV + k8 + c + 4];
                mma_tf32(acc_o[nt], af, bf);
            }
        }
        __syncthreads();   // smem reads done before next chunk's stores
    }

    // ---- epilogue: /l, transpose via smem, coalesced store ----
    float inv[2] = {1.f / l_run[0], 1.f / l_run[1]};
    float* Pf = (float*)Ps;
#pragma unroll
    for (int nt = 0; nt < 8; ++nt) {
#pragma unroll
        for (int jj = 0; jj < 4; ++jj) {
            int n = nt * 8 + 2 * c + (jj & 1);
            int m = wid * 16 + r + (jj >> 1) * 8;
            Pf[n * FSA + m] = acc_o[nt][jj] * inv[jj >> 1];
        }
    }
    __syncthreads();
    {
        int row = tid >> 2;          // 0..63 (output channel)
        int mq  = (tid & 3) * 4;
#pragma unroll
        for (int j = 0; j < 8; ++j) {
            int m = mq + 16 * j;
            *(float4*)&O[((size_t)bh * KC + row) * TT + m0 + m] =
                *(float4*)&Pf[row * FSA + m];
        }
    }
}

// ============================================================================
// Fused FiLM GEMM (unchanged from R5 — already 1.5 LDS words/MMA)
// ============================================================================
#define FILM_SMEM ((3 * 2 * 16 * SA) * 4)

__global__ __launch_bounds__(512)
void film_gemm(const float* __restrict__ Wf, const float* __restrict__ Yin,
               const float* __restrict__ bfilm, const float* __restrict__ x,
               const float* __restrict__ xmask, float* __restrict__ out)
{
    extern __shared__ uint32_t smf[];
    uint32_t* AsG = smf;
    uint32_t* AsB = smf + 2 * 16 * SA;
    uint32_t* Bs  = smf + 4 * 16 * SA;

    const int tid = threadIdx.x;
    const int bz  = blockIdx.z;
    const float* Bb = Yin + (size_t)bz * CH * TT;
    const int m0 = blockIdx.y * 128, n0 = blockIdx.x * 128;

    const int wid = tid >> 5, lane = tid & 31;
    const int wm = wid >> 2, wn = wid & 3;
    const int r = lane >> 2, c = lane & 3;

    const int l_row = tid >> 5;
    const int l_col = lane * 4;
    const int l_am  = tid >> 2;
    const int l_ak  = (tid & 3) * 4;

    float acc_g[2][4][4] = {};
    float acc_b[2][4][4] = {};

    float4 bvr, agr, abr;
#define LDG_TILE_F(k0)                                                                  \
    {                                                                                   \
        bvr = *(const float4*)&Bb[(size_t)((k0) + l_row) * TT + n0 + l_col];            \
        agr = *(const float4*)&Wf[(size_t)(m0 + l_am) * CH + (k0) + l_ak];              \
        abr = *(const float4*)&Wf[(size_t)(256 + m0 + l_am) * CH + (k0) + l_ak];        \
    }
#define STS_TILE_F(buf)                                                                 \
    {                                                                                   \
        uint4 bu; bu.x = f2tf(bvr.x); bu.y = f2tf(bvr.y); bu.z = f2tf(bvr.z); bu.w = f2tf(bvr.w); \
        *(uint4*)&Bs[(buf) * 16 * SA + l_row * SA + l_col] = bu;                        \
        AsG[(buf) * 16 * SA + (l_ak + 0) * SA + l_am] = f2tf(agr.x);                    \
        AsG[(buf) * 16 * SA + (l_ak + 1) * SA + l_am] = f2tf(agr.y);                    \
        AsG[(buf) * 16 * SA + (l_ak + 2) * SA + l_am] = f2tf(agr.z);                    \
        AsG[(buf) * 16 * SA + (l_ak + 3) * SA + l_am] = f2tf(agr.w);                    \
        AsB[(buf) * 16 * SA + (l_ak + 0) * SA + l_am] = f2tf(abr.x);                    \
        AsB[(buf) * 16 * SA + (l_ak + 1) * SA + l_am] = f2tf(abr.y);                    \
        AsB[(buf) * 16 * SA + (l_ak + 2) * SA + l_am] = f2tf(abr.z);                    \
        AsB[(buf) * 16 * SA + (l_ak + 3) * SA + l_am] = f2tf(abr.w);                    \
    }

    LDG_TILE_F(0);
    STS_TILE_F(0);
    __syncthreads();

    const int nk = CH / 16;
    for (int kb = 0; kb < nk; ++kb) {
        const int cur = kb & 1;
        const bool more = (kb + 1 < nk);
        if (more) LDG_TILE_F((kb + 1) * 16);

#pragma unroll
        for (int k8 = 0; k8 < 16; k8 += 8) {
            uint32_t afg[2][4], afb[2][4], bf[4][2];
#pragma unroll
            for (int mt = 0; mt < 2; ++mt) {
                int mbx = wm * 32 + mt * 16 + r;
                afg[mt][0] = AsG[cur * 16 * SA + (k8 + c) * SA + mbx];
                afg[mt][1] = AsG[cur * 16 * SA + (k8 + c) * SA + mbx + 8];
                afg[mt][2] = AsG[cur * 16 * SA + (k8 + c + 4) * SA + mbx];
                afg[mt][3] = AsG[cur * 16 * SA + (k8 + c + 4) * SA + mbx + 8];
                afb[mt][0] = AsB[cur * 16 * SA + (k8 + c) * SA + mbx];
                afb[mt][1] = AsB[cur * 16 * SA + (k8 + c) * SA + mbx + 8];
                afb[mt][2] = AsB[cur * 16 * SA + (k8 + c + 4) * SA + mbx];
                afb[mt][3] = AsB[cur * 16 * SA + (k8 + c + 4) * SA + mbx + 8];
            }
#pragma unroll
            for (int nt = 0; nt < 4; ++nt) {
                int nb = wn * 32 + nt * 8 + r;
                bf[nt][0] = Bs[cur * 16 * SA + (k8 + c) * SA + nb];
                bf[nt][1] = Bs[cur * 16 * SA + (k8 + c + 4) * SA + nb];
            }
#pragma unroll
            for (int mt = 0; mt < 2; ++mt)
#pragma unroll
                for (int nt = 0; nt < 4; ++nt) {
                    mma_tf32(acc_g[mt][nt], afg[mt], bf[nt]);
                    mma_tf32(acc_b[mt][nt], afb[mt], bf[nt]);
                }
        }
        if (more) STS_TILE_F(cur ^ 1);
        __syncthreads();
    }
#undef LDG_TILE_F
#undef STS_TILE_F

#pragma unroll
    for (int mt = 0; mt < 2; ++mt) {
#pragma unroll
        for (int h = 0; h < 2; ++h) {
            const int row = m0 + wm * 32 + mt * 16 + r + h * 8;
            float bg = bfilm[row];
            float bb = bfilm[256 + row];
#pragma unroll
            for (int nt = 0; nt < 4; ++nt) {
                const int col = n0 + wn * 32 + nt * 8 + c * 2;
                float g0  = acc_g[mt][nt][h * 2 + 0] + bg;
                float g1  = acc_g[mt][nt][h * 2 + 1] + bg;
                float be0 = acc_b[mt][nt][h * 2 + 0] + bb;
                float be1 = acc_b[mt][nt][h * 2 + 1] + bb;
                float2 xv = *(const float2*)&x[((size_t)bz * CH + row) * TT + col];
                float xmm0 = xmask[(size_t)bz * TT + col];
                float xmm1 = xmask[(size_t)bz * TT + col + 1];
                float2 o;
                o.x = (xv.x * g0 + be0) * xmm0;
                o.y = (xv.y * g1 + be1) * xmm1;
                *(float2*)&out[((size_t)bz * CH + row) * TT + col] = o;
            }
        }
    }
}

// ---------------- launch ----------------
extern "C" void kernel_launch(void* const* d_in, const int* in_sizes, int n_in,
                              void* d_out, int out_size) {
    const float* x           = (const float*)d_in[0];
    const float* x_mask      = (const float*)d_in[1];
    const float* cond_latent = (const float*)d_in[2];
    const float* cond_mask   = (const float*)d_in[3];
    const float* w_cond      = (const float*)d_in[4];
    const float* b_cond      = (const float*)d_in[5];
    const float* wq          = (const float*)d_in[6];
    const float* bq          = (const float*)d_in[7];
    const float* wk          = (const float*)d_in[8];
    const float* bk          = (const float*)d_in[9];
    const float* wv          = (const float*)d_in[10];
    const float* bv          = (const float*)d_in[11];
    const float* wo          = (const float*)d_in[12];
    const float* bo          = (const float*)d_in[13];
    const float* w_film      = (const float*)d_in[14];
    const float* b_film      = (const float*)d_in[15];
    float* out = (float*)d_out;

    float *p_c, *p_q, *p_k, *p_v, *p_att, *p_y;
    cudaGetSymbolAddress((void**)&p_c,   g_c);
    cudaGetSymbolAddress((void**)&p_q,   g_q);
    cudaGetSymbolAddress((void**)&p_k,   g_k);
    cudaGetSymbolAddress((void**)&p_v,   g_v);
    cudaGetSymbolAddress((void**)&p_att, g_att);
    cudaGetSymbolAddress((void**)&p_y,   g_y);

    cudaFuncSetAttribute(flash_attn, cudaFuncAttributeMaxDynamicSharedMemorySize, FLASH_SMEM);
    cudaFuncSetAttribute(film_gemm,  cudaFuncAttributeMaxDynamicSharedMemorySize, FILM_SMEM);

    // RoPE tables [d][t]
    rope_table_kernel<<<(32 * TT + 255) / 256, 256>>>();

    // c = w_cond @ cond_latent + b_cond     [b][256][512]
    mma_gemm64<0><<<dim3(TSL / 128, CH / 128, BQ), 256>>>(
        w_cond, nullptr, cond_latent, b_cond, nullptr, p_c, nullptr,
        TSL, CONDC, (size_t)CONDC * TSL, (size_t)CH * TSL);

    // q = wq @ x + bq                        [b][256][2048]
    mma_gemm64<0><<<dim3(TT / 128, CH / 128, BQ), 256>>>(
        wq, nullptr, x, bq, nullptr, p_q, nullptr,
        TT, CH, (size_t)CH * TT, (size_t)CH * TT);

    // k and v fused in one launch
    mma_gemm64<1><<<dim3(TSL / 128, CH / 128, 2 * BQ), 256>>>(
        wk, wv, p_c, bk, bv, p_k, p_v,
        TSL, CH, (size_t)CH * TSL, (size_t)CH * TSL);

    // pre-rope + cond-mask K in place
    rope_k_mask_kernel<<<(BQ * NH * 32 * TSL + 255) / 256, 256>>>(p_k, cond_mask);

    // fused attention (Q-rope + scores + bias-mask + softmax + P@V)
    flash_attn<<<dim3(1, TT / 128, BQ * NH), 256, FLASH_SMEM>>>(
        p_q, p_k, p_v, cond_mask, p_att);

    // y = wo @ att + bo
    mma_gemm64<0><<<dim3(TT / 128, CH / 128, BQ), 256>>>(
        wo, nullptr, p_att, bo, nullptr, p_y, nullptr,
        TT, CH, (size_t)CH * TT, (size_t)CH * TT);

    // fused FiLM
    film_gemm<<<dim3(TT / 128, CH / 128, BQ), 512, FILM_SMEM>>>(
        w_film, p_y, b_film, x, x_mask, out);
}

// round 7
// speedup vs baseline: 2.9112x; 1.0060x over previous
#include <cuda_runtime.h>
#include <math.h>
#include <stdint.h>

// ---------------- problem constants (fixed shapes) ----------------
#define BQ   16      // batch
#define CH   256     // hidden
#define CONDC 512    // cond channels
#define TT   2048    // target length
#define TSL  512     // source length
#define NH   4       // heads
#define KC   64      // head dim

#define SA 136       // padded smem stride (words): mod 32 = 8 (CF fragment loads), *4 % 16 == 0

// ---------------- scratch (device globals; no allocation) ----------------
__device__ float g_c  [BQ * CH * TSL];        // cond proj           [b][C][Ts]
__device__ float g_q  [BQ * CH * TT];         // q (un-roped)        [bh][64][Tt]
__device__ float g_k  [BQ * CH * TSL];        // k (roped+masked)    [bh][64][Ts]
__device__ float g_v  [BQ * CH * TSL];        // v                   [bh][64][Ts]
__device__ float g_att[BQ * CH * TT];         // attn out            [b][C][Tt]
__device__ float g_y  [BQ * CH * TT];         // wo proj             [b][C][Tt]
__device__ float g_cos[32 * TT];              // [d][t]
__device__ float g_sin[32 * TT];

// ---------------- tf32 helpers ----------------
__device__ __forceinline__ uint32_t f2tf(float f) {
    uint32_t u;
    asm("cvt.rna.tf32.f32 %0, %1;" : "=r"(u) : "f"(f));
    return u;
}

__device__ __forceinline__ void mma_tf32(float* c, const uint32_t* a, const uint32_t* b) {
    asm volatile(
        "mma.sync.aligned.m16n8k8.row.col.f32.tf32.tf32.f32 "
        "{%0,%1,%2,%3}, {%4,%5,%6,%7}, {%8,%9}, {%0,%1,%2,%3};\n"
        : "+f"(c[0]), "+f"(c[1]), "+f"(c[2]), "+f"(c[3])
        : "r"(a[0]), "r"(a[1]), "r"(a[2]), "r"(a[3]), "r"(b[0]), "r"(b[1]));
}

// ---------------- RoPE tables, layout [d][t] ----------------
__global__ void rope_table_kernel() {
    int idx = blockIdx.x * blockDim.x + threadIdx.x;
    if (idx >= 32 * TT) return;
    int d = idx / TT;
    int t = idx % TT;
    float invf = (float)pow(10000.0, -(double)d / 32.0);
    float ang  = (float)t * invf;            // same fp32 rounding as reference
    g_cos[idx] = (float)cos((double)ang);
    g_sin[idx] = (float)sin((double)ang);
}

// ---------------- pre-rope + mask K in place: [bh][64][Ts] ----------------
__global__ void rope_k_mask_kernel(float* __restrict__ k, const float* __restrict__ cmask) {
    int idx = blockIdx.x * blockDim.x + threadIdx.x;
    if (idx >= BQ * NH * 32 * TSL) return;
    int t  = idx & (TSL - 1);
    int rr = idx >> 9;            // TSL = 512
    int d  = rr & 31;
    int bh = rr >> 5;
    int b  = bh >> 2;
    float cs = g_cos[d * TT + t];
    float sn = g_sin[d * TT + t];
    float cm = cmask[(size_t)b * TSL + t];
    size_t base = ((size_t)bh * KC + d) * TSL + t;
    float k1 = k[base];
    float k2 = k[base + (size_t)32 * TSL];
    k[base]                    = (k1 * cs - k2 * sn) * cm;
    k[base + (size_t)32 * TSL] = (k2 * cs + k1 * sn) * cm;
}

// ============================================================================
// tf32 MMA GEMM, 128x128 CTA tile, 256 threads (8 warps, 2x4 grid),
// warp tile 64x32, BK=32 (64 MMAs/warp per barrier), double-buffered
// dynamic smem (68 KB), conflict-free A transpose-store via xor-16 remap.
// A stored [M][K] global. Y = A@B + bias[m].
// GSEL: 0 = plain; 1 = kv-fused (blockIdx.z>>4 selects wk/wv set).
// ============================================================================
#define GEMM_SMEM (4 * 32 * SA * 4)   // As[2][32*SA] + Bs[2][32*SA] words

template<int GSEL>
__global__ __launch_bounds__(256, 2)
void mma_gemm64(const float* __restrict__ A0, const float* __restrict__ A1,
                const float* __restrict__ B,
                const float* __restrict__ bias0, const float* __restrict__ bias1,
                float* __restrict__ Y0, float* __restrict__ Y1,
                int Ndim, int Kdim, size_t strideB, size_t strideY)
{
    extern __shared__ uint32_t smg[];
    uint32_t* Asm = smg;                 // [2][32*SA]
    uint32_t* Bsm = smg + 2 * 32 * SA;   // [2][32*SA]

    const int tid = threadIdx.x;
    int bz, sel = 0;
    if (GSEL == 1) { bz = blockIdx.z & 15; sel = blockIdx.z >> 4; }
    else           { bz = blockIdx.z; }
    const float* A    = (GSEL == 1 && sel) ? A1 : A0;
    const float* bias = (GSEL == 1 && sel) ? bias1 : bias0;
    float*       Y    = (GSEL == 1 && sel) ? Y1 : Y0;
    const float* Bb = B + (size_t)bz * strideB;
    float*       Yb = Y + (size_t)bz * strideY;
    const int m0 = blockIdx.y * 128, n0 = blockIdx.x * 128;

    const int wid = tid >> 5, lane = tid & 31;
    const int wm = wid >> 2, wn = wid & 3;       // 2x4 warp grid, 64x32 warp tile
    const int r = lane >> 2, c = lane & 3;

    // A loader: row a_m, k-half a_k (xor-16 remap -> CF scalar STS)
    const int a_m = ((tid >> 1) + ((tid & 1) << 4)) & 127;
    const int a_k = (tid & 1) << 4;
    // B loader: row b_row, 4 uint4 at word cols b_c4 + 32*j
    const int b_row = tid >> 3;          // 0..31
    const int b_c4  = (tid & 7) * 4;     // 0..28

    float acc[4][4][4] = {};
    const int nk = Kdim / 32;

    float4 avr[4], bvr[4];
#define LDG_T(k0)                                                                       \
    {                                                                                   \
        _Pragma("unroll")                                                               \
        for (int j = 0; j < 4; ++j) {                                                   \
            avr[j] = *(const float4*)&A[(size_t)(m0 + a_m) * Kdim + (k0) + a_k + 4 * j];\
            bvr[j] = *(const float4*)&Bb[(size_t)((k0) + b_row) * Ndim + n0 + b_c4 + 32 * j]; \
        }                                                                               \
    }
#define STS_T(buf)                                                                      \
    {                                                                                   \
        uint32_t* Ab = Asm + (buf) * 32 * SA;                                           \
        uint32_t* Bd = Bsm + (buf) * 32 * SA;                                           \
        _Pragma("unroll")                                                               \
        for (int j = 0; j < 4; ++j) {                                                   \
            Ab[(a_k + 4 * j + 0) * SA + a_m] = f2tf(avr[j].x);                          \
            Ab[(a_k + 4 * j + 1) * SA + a_m] = f2tf(avr[j].y);                          \
            Ab[(a_k + 4 * j + 2) * SA + a_m] = f2tf(avr[j].z);                          \
            Ab[(a_k + 4 * j + 3) * SA + a_m] = f2tf(avr[j].w);                          \
            uint4 bu;                                                                   \
            bu.x = f2tf(bvr[j].x); bu.y = f2tf(bvr[j].y);                               \
            bu.z = f2tf(bvr[j].z); bu.w = f2tf(bvr[j].w);                               \
            *(uint4*)&Bd[b_row * SA + b_c4 + 32 * j] = bu;                              \
        }                                                                               \
    }

    LDG_T(0);
    STS_T(0);
    __syncthreads();

    for (int kb = 0; kb < nk; ++kb) {
        const int cur = kb & 1;
        const bool more = (kb + 1 < nk);
        if (more) LDG_T((kb + 1) * 32);

        const uint32_t* Ac = Asm + cur * 32 * SA;
        const uint32_t* Bc = Bsm + cur * 32 * SA;
#pragma unroll
        for (int k8 = 0; k8 < 32; k8 += 8) {
            uint32_t af[4][4], bf[4][2];
#pragma unroll
            for (int mt = 0; mt < 4; ++mt) {
                int mb = wm * 64 + mt * 16 + r;
                af[mt][0] = Ac[(k8 + c) * SA + mb];
                af[mt][1] = Ac[(k8 + c) * SA + mb + 8];
                af[mt][2] = Ac[(k8 + c + 4) * SA + mb];
                af[mt][3] = Ac[(k8 + c + 4) * SA + mb + 8];
            }
#pragma unroll
            for (int nt = 0; nt < 4; ++nt) {
                int nb = wn * 32 + nt * 8 + r;
                bf[nt][0] = Bc[(k8 + c) * SA + nb];
                bf[nt][1] = Bc[(k8 + c + 4) * SA + nb];
            }
#pragma unroll
            for (int mt = 0; mt < 4; ++mt)
#pragma unroll
                for (int nt = 0; nt < 4; ++nt)
                    mma_tf32(acc[mt][nt], af[mt], bf[nt]);
        }
        if (more) STS_T(cur ^ 1);
        __syncthreads();
    }
#undef LDG_T
#undef STS_T

#pragma unroll
    for (int mt = 0; mt < 4; ++mt) {
#pragma unroll
        for (int h = 0; h < 2; ++h) {
            const int row = m0 + wm * 64 + mt * 16 + h * 8 + r;
            float bval = bias[row];
#pragma unroll
            for (int nt = 0; nt < 4; ++nt) {
                const int col = n0 + wn * 32 + nt * 8 + c * 2;
                float2 o;
                o.x = acc[mt][nt][h * 2 + 0] + bval;
                o.y = acc[mt][nt][h * 2 + 1] + bval;
                *(float2*)&Yb[(size_t)row * Ndim + col] = o;
            }
        }
    }
}

// ============================================================================
// Fused flash attention (unchanged from R6)
// ============================================================================
#define FSA 136
#define FSK 72
#define FSV 68
#define FLASH_SMEM ((64*FSA + 64*FSK + 64*FSV + 64*FSA + 512) * 4)

__global__ __launch_bounds__(256, 2)
void flash_attn(const float* __restrict__ Qg, const float* __restrict__ Kg,
                const float* __restrict__ Vg, const float* __restrict__ cmask,
                float* __restrict__ O)
{
    extern __shared__ uint32_t sm[];
    uint32_t* Qs  = sm;                    // [64][136]
    uint32_t* Ks  = sm + 64 * FSA;         // [64][72]   [d][n]
    uint32_t* Vs  = Ks + 64 * FSK;         // [64][68]   [ch][pos]
    uint32_t* Ps  = Vs + 64 * FSV;         // [64][136]  [k][m] / f32 [n][m] epilogue
    float*    cmb = (float*)(Ps + 64 * FSA);  // [512] additive bias

    const int bh = blockIdx.z;
    const int b  = bh >> 2;
    const int m0 = blockIdx.y * 128;
    const int tid = threadIdx.x, wid = tid >> 5, lane = tid & 31;
    const int r = lane >> 2, c = lane & 3;
    const int mb = wid * 16 + r;

    const float* Qb = Qg + (size_t)bh * KC * TT;
    const float* Kb = Kg + (size_t)bh * KC * TSL;
    const float* Vb = Vg + (size_t)bh * KC * TSL;

    // ---- load Q tile (64 x 128) with RoPE ----
    {
        int d  = tid >> 3;          // 0..31
        int mg = (tid & 7) * 16;
#pragma unroll
        for (int j = 0; j < 16; j += 4) {
            int m = mg + j;
            int t = m0 + m;
            float4 q1 = *(const float4*)&Qb[(size_t)d * TT + t];
            float4 q2 = *(const float4*)&Qb[(size_t)(d + 32) * TT + t];
            float4 cv = *(const float4*)&g_cos[(size_t)d * TT + t];
            float4 sv = *(const float4*)&g_sin[(size_t)d * TT + t];
            Qs[d * FSA + m + 0] = f2tf(q1.x * cv.x - q2.x * sv.x);
            Qs[d * FSA + m + 1] = f2tf(q1.y * cv.y - q2.y * sv.y);
            Qs[d * FSA + m + 2] = f2tf(q1.z * cv.z - q2.z * sv.z);
            Qs[d * FSA + m + 3] = f2tf(q1.w * cv.w - q2.w * sv.w);
            Qs[(d + 32) * FSA + m + 0] = f2tf(q2.x * cv.x + q1.x * sv.x);
            Qs[(d + 32) * FSA + m + 1] = f2tf(q2.y * cv.y + q1.y * sv.y);
            Qs[(d + 32) * FSA + m + 2] = f2tf(q2.z * cv.z + q1.z * sv.z);
            Qs[(d + 32) * FSA + m + 3] = f2tf(q2.w * cv.w + q1.w * sv.w);
        }
    }
    // ---- cmask -> additive bias in smem ----
    for (int i = tid; i < TSL; i += 256)
        cmb[i] = (cmask[(size_t)b * TSL + i] == 0.f) ? -1e4f : 0.f;

    // ---- prefetch chunk 0 into registers ----
    const int prow = tid >> 2;          // 0..63
    const int pcol = (tid & 3) * 4;     // col = pcol + 16*j
    float4 kr[4], vr[4];
#pragma unroll
    for (int j = 0; j < 4; ++j) {
        kr[j] = *(const float4*)&Kb[(size_t)prow * TSL + pcol + 16 * j];
        vr[j] = *(const float4*)&Vb[(size_t)prow * TSL + pcol + 16 * j];
    }

    float m_run[2] = {-1e30f, -1e30f};
    float l_run[2] = {0.f, 0.f};
    float acc_o[8][4] = {};

    __syncthreads();   // Qs + cmb visible

    for (int ci = 0; ci < 8; ++ci) {
        const int s0 = ci * 64;
        // ---- store prefetched K/V into smem (tf32) ----
#pragma unroll
        for (int j = 0; j < 4; ++j) {
            int col = pcol + 16 * j;
            Ks[prow * FSK + col + 0] = f2tf(kr[j].x);
            Ks[prow * FSK + col + 1] = f2tf(kr[j].y);
            Ks[prow * FSK + col + 2] = f2tf(kr[j].z);
            Ks[prow * FSK + col + 3] = f2tf(kr[j].w);
            Vs[prow * FSV + col + 0] = f2tf(vr[j].x);
            Vs[prow * FSV + col + 1] = f2tf(vr[j].y);
            Vs[prow * FSV + col + 2] = f2tf(vr[j].z);
            Vs[prow * FSV + col + 3] = f2tf(vr[j].w);
        }
        __syncthreads();
        // ---- prefetch next chunk ----
        if (ci < 7) {
#pragma unroll
            for (int j = 0; j < 4; ++j) {
                kr[j] = *(const float4*)&Kb[(size_t)prow * TSL + s0 + 64 + pcol + 16 * j];
                vr[j] = *(const float4*)&Vb[(size_t)prow * TSL + s0 + 64 + pcol + 16 * j];
            }
        }

        // ---- S = Q^T K : warp tile 16 x 64 ----
        float acc_s[8][4] = {};
#pragma unroll
        for (int k8 = 0; k8 < 64; k8 += 8) {
            uint32_t af[4];
            af[0] = Qs[(k8 + c) * FSA + mb];
            af[1] = Qs[(k8 + c) * FSA + mb + 8];
            af[2] = Qs[(k8 + c + 4) * FSA + mb];
            af[3] = Qs[(k8 + c + 4) * FSA + mb + 8];
#pragma unroll
            for (int nt = 0; nt < 8; ++nt) {
                uint32_t bf[2];
                bf[0] = Ks[(k8 + c) * FSK + nt * 8 + r];
                bf[1] = Ks[(k8 + c + 4) * FSK + nt * 8 + r];
                mma_tf32(acc_s[nt], af, bf);
            }
        }

        // ---- scale + bias + online softmax (warp-local rows) ----
        float mx[2] = {-1e30f, -1e30f};
#pragma unroll
        for (int nt = 0; nt < 8; ++nt) {
            float2 bias = *(float2*)&cmb[s0 + nt * 8 + 2 * c];
#pragma unroll
            for (int jj = 0; jj < 4; ++jj) {
                float v = acc_s[nt][jj] * 0.125f + ((jj & 1) ? bias.y : bias.x);
                acc_s[nt][jj] = v;
                mx[jj >> 1] = fmaxf(mx[jj >> 1], v);
            }
        }
#pragma unroll
        for (int h = 0; h < 2; ++h) {
            mx[h] = fmaxf(mx[h], __shfl_xor_sync(0xffffffffu, mx[h], 1));
            mx[h] = fmaxf(mx[h], __shfl_xor_sync(0xffffffffu, mx[h], 2));
        }
        float mnew[2], scale[2], lad[2] = {0.f, 0.f};
#pragma unroll
        for (int h = 0; h < 2; ++h) {
            mnew[h]  = fmaxf(m_run[h], mx[h]);
            scale[h] = __expf(m_run[h] - mnew[h]);
            m_run[h] = mnew[h];
        }
#pragma unroll
        for (int nt = 0; nt < 8; ++nt) {
#pragma unroll
            for (int jj = 0; jj < 4; ++jj) {
                float e = __expf(acc_s[nt][jj] - mnew[jj >> 1]);
                acc_s[nt][jj] = e;
                lad[jj >> 1] += e;
            }
        }
#pragma unroll
        for (int h = 0; h < 2; ++h) {
            lad[h] += __shfl_xor_sync(0xffffffffu, lad[h], 1);
            lad[h] += __shfl_xor_sync(0xffffffffu, lad[h], 2);
            l_run[h] = l_run[h] * scale[h] + lad[h];
        }
#pragma unroll
        for (int nt = 0; nt < 8; ++nt) {
#pragma unroll
            for (int jj = 0; jj < 4; ++jj)
                acc_o[nt][jj] *= scale[jj >> 1];
        }
        // P -> smem [k][m] (warp-private m-stripe)
#pragma unroll
        for (int nt = 0; nt < 8; ++nt) {
#pragma unroll
            for (int jj = 0; jj < 4; ++jj) {
                int kcol = nt * 8 + 2 * c + (jj & 1);
                int mrow = wid * 16 + r + (jj >> 1) * 8;
                Ps[kcol * FSA + mrow] = f2tf(acc_s[nt][jj]);
            }
        }
        __syncwarp();

        // ---- O += P @ V^T ----
#pragma unroll
        for (int k8 = 0; k8 < 64; k8 += 8) {
            uint32_t af[4];
            af[0] = Ps[(k8 + c) * FSA + mb];
            af[1] = Ps[(k8 + c) * FSA + mb + 8];
            af[2] = Ps[(k8 + c + 4) * FSA + mb];
            af[3] = Ps[(k8 + c + 4) * FSA + mb + 8];
#pragma unroll
            for (int nt = 0; nt < 8; ++nt) {
                uint32_t bf[2];
                bf[0] = Vs[(nt * 8 + r) * FSV + k8 + c];
                bf[1] = Vs[(nt * 8 + r) * FSV + k8 + c + 4];
                mma_tf32(acc_o[nt], af, bf);
            }
        }
        __syncthreads();   // smem reads done before next chunk's stores
    }

    // ---- epilogue: /l, transpose via smem, coalesced store ----
    float inv[2] = {1.f / l_run[0], 1.f / l_run[1]};
    float* Pf = (float*)Ps;
#pragma unroll
    for (int nt = 0; nt < 8; ++nt) {
#pragma unroll
        for (int jj = 0; jj < 4; ++jj) {
            int n = nt * 8 + 2 * c + (jj & 1);
            int m = wid * 16 + r + (jj >> 1) * 8;
            Pf[n * FSA + m] = acc_o[nt][jj] * inv[jj >> 1];
        }
    }
    __syncthreads();
    {
        int row = tid >> 2;          // 0..63 (output channel)
        int mq  = (tid & 3) * 4;
#pragma unroll
        for (int j = 0; j < 8; ++j) {
            int m = mq + 16 * j;
            *(float4*)&O[((size_t)bh * KC + row) * TT + m0 + m] =
                *(float4*)&Pf[row * FSA + m];
        }
    }
}

// ============================================================================
// Fused FiLM GEMM (unchanged from R6)
// ============================================================================
#define FILM_SMEM ((3 * 2 * 16 * SA) * 4)

__global__ __launch_bounds__(512)
void film_gemm(const float* __restrict__ Wf, const float* __restrict__ Yin,
               const float* __restrict__ bfilm, const float* __restrict__ x,
               const float* __restrict__ xmask, float* __restrict__ out)
{
    extern __shared__ uint32_t smf[];
    uint32_t* AsG = smf;
    uint32_t* AsB = smf + 2 * 16 * SA;
    uint32_t* Bs  = smf + 4 * 16 * SA;

    const int tid = threadIdx.x;
    const int bz  = blockIdx.z;
    const float* Bb = Yin + (size_t)bz * CH * TT;
    const int m0 = blockIdx.y * 128, n0 = blockIdx.x * 128;

    const int wid = tid >> 5, lane = tid & 31;
    const int wm = wid >> 2, wn = wid & 3;
    const int r = lane >> 2, c = lane & 3;

    const int l_row = tid >> 5;
    const int l_col = lane * 4;
    const int l_am  = tid >> 2;
    const int l_ak  = (tid & 3) * 4;

    float acc_g[2][4][4] = {};
    float acc_b[2][4][4] = {};

    float4 bvr, agr, abr;
#define LDG_TILE_F(k0)                                                                  \
    {                                                                                   \
        bvr = *(const float4*)&Bb[(size_t)((k0) + l_row) * TT + n0 + l_col];            \
        agr = *(const float4*)&Wf[(size_t)(m0 + l_am) * CH + (k0) + l_ak];              \
        abr = *(const float4*)&Wf[(size_t)(256 + m0 + l_am) * CH + (k0) + l_ak];        \
    }
#define STS_TILE_F(buf)                                                                 \
    {                                                                                   \
        uint4 bu; bu.x = f2tf(bvr.x); bu.y = f2tf(bvr.y); bu.z = f2tf(bvr.z); bu.w = f2tf(bvr.w); \
        *(uint4*)&Bs[(buf) * 16 * SA + l_row * SA + l_col] = bu;                        \
        AsG[(buf) * 16 * SA + (l_ak + 0) * SA + l_am] = f2tf(agr.x);                    \
        AsG[(buf) * 16 * SA + (l_ak + 1) * SA + l_am] = f2tf(agr.y);                    \
        AsG[(buf) * 16 * SA + (l_ak + 2) * SA + l_am] = f2tf(agr.z);                    \
        AsG[(buf) * 16 * SA + (l_ak + 3) * SA + l_am] = f2tf(agr.w);                    \
        AsB[(buf) * 16 * SA + (l_ak + 0) * SA + l_am] = f2tf(abr.x);                    \
        AsB[(buf) * 16 * SA + (l_ak + 1) * SA + l_am] = f2tf(abr.y);                    \
        AsB[(buf) * 16 * SA + (l_ak + 2) * SA + l_am] = f2tf(abr.z);                    \
        AsB[(buf) * 16 * SA + (l_ak + 3) * SA + l_am] = f2tf(abr.w);                    \
    }

    LDG_TILE_F(0);
    STS_TILE_F(0);
    __syncthreads();

    const int nk = CH / 16;
    for (int kb = 0; kb < nk; ++kb) {
        const int cur = kb & 1;
        const bool more = (kb + 1 < nk);
        if (more) LDG_TILE_F((kb + 1) * 16);

#pragma unroll
        for (int k8 = 0; k8 < 16; k8 += 8) {
            uint32_t afg[2][4], afb[2][4], bf[4][2];
#pragma unroll
            for (int mt = 0; mt < 2; ++mt) {
                int mbx = wm * 32 + mt * 16 + r;
                afg[mt][0] = AsG[cur * 16 * SA + (k8 + c) * SA + mbx];
                afg[mt][1] = AsG[cur * 16 * SA + (k8 + c) * SA + mbx + 8];
                afg[mt][2] = AsG[cur * 16 * SA + (k8 + c + 4) * SA + mbx];
                afg[mt][3] = AsG[cur * 16 * SA + (k8 + c + 4) * SA + mbx + 8];
                afb[mt][0] = AsB[cur * 16 * SA + (k8 + c) * SA + mbx];
                afb[mt][1] = AsB[cur * 16 * SA + (k8 + c) * SA + mbx + 8];
                afb[mt][2] = AsB[cur * 16 * SA + (k8 + c + 4) * SA + mbx];
                afb[mt][3] = AsB[cur * 16 * SA + (k8 + c + 4) * SA + mbx + 8];
            }
#pragma unroll
            for (int nt = 0; nt < 4; ++nt) {
                int nb = wn * 32 + nt * 8 + r;
                bf[nt][0] = Bs[cur * 16 * SA + (k8 + c) * SA + nb];
                bf[nt][1] = Bs[cur * 16 * SA + (k8 + c + 4) * SA + nb];
            }
#pragma unroll
            for (int mt = 0; mt < 2; ++mt)
#pragma unroll
                for (int nt = 0; nt < 4; ++nt) {
                    mma_tf32(acc_g[mt][nt], afg[mt], bf[nt]);
                    mma_tf32(acc_b[mt][nt], afb[mt], bf[nt]);
                }
        }
        if (more) STS_TILE_F(cur ^ 1);
        __syncthreads();
    }
#undef LDG_TILE_F
#undef STS_TILE_F

#pragma unroll
    for (int mt = 0; mt < 2; ++mt) {
#pragma unroll
        for (int h = 0; h < 2; ++h) {
            const int row = m0 + wm * 32 + mt * 16 + r + h * 8;
            float bg = bfilm[row];
            float bb = bfilm[256 + row];
#pragma unroll
            for (int nt = 0; nt < 4; ++nt) {
                const int col = n0 + wn * 32 + nt * 8 + c * 2;
                float g0  = acc_g[mt][nt][h * 2 + 0] + bg;
                float g1  = acc_g[mt][nt][h * 2 + 1] + bg;
                float be0 = acc_b[mt][nt][h * 2 + 0] + bb;
                float be1 = acc_b[mt][nt][h * 2 + 1] + bb;
                float2 xv = *(const float2*)&x[((size_t)bz * CH + row) * TT + col];
                float xmm0 = xmask[(size_t)bz * TT + col];
                float xmm1 = xmask[(size_t)bz * TT + col + 1];
                float2 o;
                o.x = (xv.x * g0 + be0) * xmm0;
                o.y = (xv.y * g1 + be1) * xmm1;
                *(float2*)&out[((size_t)bz * CH + row) * TT + col] = o;
            }
        }
    }
}

// ---------------- launch ----------------
extern "C" void kernel_launch(void* const* d_in, const int* in_sizes, int n_in,
                              void* d_out, int out_size) {
    const float* x           = (const float*)d_in[0];
    const float* x_mask      = (const float*)d_in[1];
    const float* cond_latent = (const float*)d_in[2];
    const float* cond_mask   = (const float*)d_in[3];
    const float* w_cond      = (const float*)d_in[4];
    const float* b_cond      = (const float*)d_in[5];
    const float* wq          = (const float*)d_in[6];
    const float* bq          = (const float*)d_in[7];
    const float* wk          = (const float*)d_in[8];
    const float* bk          = (const float*)d_in[9];
    const float* wv          = (const float*)d_in[10];
    const float* bv          = (const float*)d_in[11];
    const float* wo          = (const float*)d_in[12];
    const float* bo          = (const float*)d_in[13];
    const float* w_film      = (const float*)d_in[14];
    const float* b_film      = (const float*)d_in[15];
    float* out = (float*)d_out;

    float *p_c, *p_q, *p_k, *p_v, *p_att, *p_y;
    cudaGetSymbolAddress((void**)&p_c,   g_c);
    cudaGetSymbolAddress((void**)&p_q,   g_q);
    cudaGetSymbolAddress((void**)&p_k,   g_k);
    cudaGetSymbolAddress((void**)&p_v,   g_v);
    cudaGetSymbolAddress((void**)&p_att, g_att);
    cudaGetSymbolAddress((void**)&p_y,   g_y);

    cudaFuncSetAttribute(mma_gemm64<0>, cudaFuncAttributeMaxDynamicSharedMemorySize, GEMM_SMEM);
    cudaFuncSetAttribute(mma_gemm64<1>, cudaFuncAttributeMaxDynamicSharedMemorySize, GEMM_SMEM);
    cudaFuncSetAttribute(flash_attn,    cudaFuncAttributeMaxDynamicSharedMemorySize, FLASH_SMEM);
    cudaFuncSetAttribute(film_gemm,     cudaFuncAttributeMaxDynamicSharedMemorySize, FILM_SMEM);

    // RoPE tables [d][t]
    rope_table_kernel<<<(32 * TT + 255) / 256, 256>>>();

    // c = w_cond @ cond_latent + b_cond     [b][256][512]
    mma_gemm64<0><<<dim3(TSL / 128, CH / 128, BQ), 256, GEMM_SMEM>>>(
        w_cond, nullptr, cond_latent, b_cond, nullptr, p_c, nullptr,
        TSL, CONDC, (size_t)CONDC * TSL, (size_t)CH * TSL);

    // q = wq @ x + bq                        [b][256][2048]
    mma_gemm64<0><<<dim3(TT / 128, CH / 128, BQ), 256, GEMM_SMEM>>>(
        wq, nullptr, x, bq, nullptr, p_q, nullptr,
        TT, CH, (size_t)CH * TT, (size_t)CH * TT);

    // k and v fused in one launch
    mma_gemm64<1><<<dim3(TSL / 128, CH / 128, 2 * BQ), 256, GEMM_SMEM>>>(
        wk, wv, p_c, bk, bv, p_k, p_v,
        TSL, CH, (size_t)CH * TSL, (size_t)CH * TSL);

    // pre-rope + cond-mask K in place
    rope_k_mask_kernel<<<(BQ * NH * 32 * TSL + 255) / 256, 256>>>(p_k, cond_mask);

    // fused attention (Q-rope + scores + bias-mask + softmax + P@V)
    flash_attn<<<dim3(1, TT / 128, BQ * NH), 256, FLASH_SMEM>>>(
        p_q, p_k, p_v, cond_mask, p_att);

    // y = wo @ att + bo
    mma_gemm64<0><<<dim3(TT / 128, CH / 128, BQ), 256, GEMM_SMEM>>>(
        wo, nullptr, p_att, bo, nullptr, p_y, nullptr,
        TT, CH, (size_t)CH * TT, (size_t)CH * TT);

    // fused FiLM
    film_gemm<<<dim3(TT / 128, CH / 128, BQ), 512, FILM_SMEM>>>(
        w_film, p_y, b_film, x, x_mask, out);
}